// round 13
// baseline (speedup 1.0000x reference)
#include <cuda_runtime.h>
#include <cuda_fp16.h>
#include <cstdint>
#include <math.h>

#define Bdim 4
#define Cdim 256
#define Ndim 2304      // 48*48
#define PLANE (Bdim*Cdim*Ndim)
#define CN   (Cdim*Ndim)
#define NN   ((size_t)Ndim*Ndim)

#define BN 128
#define SKP 136        // fp16 [k][*] stride (272B)
#define VKP 72         // fp16 [row][k] stride (144B)

// ---- scratch ----
__device__ __half g_Xh[3][PLANE];                    // fp16 inputs
__device__ __half g_WT[11][Cdim * Cdim];             // fp16 weights
__device__ __half g_Kh[3][PLANE];                    // raw fp16 K
__device__ __half g_H[9][PLANE];                     // Q0..2, KS0..2, V0..2
__device__ __half g_S3h[(size_t)3 * Bdim * NN];      // scores / probs
__device__ __half g_Wh[3][PLANE];                    // attention outputs
__device__ __half g_F3h[3][PLANE];                   // gated outputs

// ---- fp16 mma + ldmatrix ----
__device__ __forceinline__ void mma_f16(float c[4], const uint32_t a[4], const uint32_t b[2]) {
    asm volatile(
        "mma.sync.aligned.m16n8k16.row.col.f32.f16.f16.f32 "
        "{%0,%1,%2,%3}, {%4,%5,%6,%7}, {%8,%9}, {%0,%1,%2,%3};"
        : "+f"(c[0]), "+f"(c[1]), "+f"(c[2]), "+f"(c[3])
        : "r"(a[0]), "r"(a[1]), "r"(a[2]), "r"(a[3]), "r"(b[0]), "r"(b[1]));
}
__device__ __forceinline__ void ldsm4(uint32_t& r0, uint32_t& r1, uint32_t& r2, uint32_t& r3, uint32_t a) {
    asm volatile("ldmatrix.sync.aligned.m8n8.x4.shared.b16 {%0,%1,%2,%3}, [%4];"
        : "=r"(r0), "=r"(r1), "=r"(r2), "=r"(r3) : "r"(a));
}
__device__ __forceinline__ void ldsm4t(uint32_t& r0, uint32_t& r1, uint32_t& r2, uint32_t& r3, uint32_t a) {
    asm volatile("ldmatrix.sync.aligned.m8n8.x4.trans.shared.b16 {%0,%1,%2,%3}, [%4];"
        : "=r"(r0), "=r"(r1), "=r"(r2), "=r"(r3) : "r"(a));
}

// ---- cp.async ----
__device__ __forceinline__ uint32_t smem_cast(const void* p) {
    return (uint32_t)__cvta_generic_to_shared(p);
}
#define CP_ASYNC16(dst_u32, gptr) \
    asm volatile("cp.async.cg.shared.global [%0], [%1], 16;" :: "r"(dst_u32), "l"(gptr))
#define CP_COMMIT() asm volatile("cp.async.commit_group;" ::: "memory")
#define CP_WAIT1()  asm volatile("cp.async.wait_group 1;" ::: "memory")
#define CP_WAIT0()  asm volatile("cp.async.wait_group 0;" ::: "memory")

#define DECL_ACC4 float acc[4][4][4]; \
    _Pragma("unroll") for (int mi = 0; mi < 4; mi++) \
    _Pragma("unroll") for (int ni = 0; ni < 4; ni++) \
    _Pragma("unroll") for (int r = 0; r < 4; r++) acc[mi][ni][r] = 0.f;

#define DECL_ACC2 float acc[2][4][4]; \
    _Pragma("unroll") for (int mi = 0; mi < 2; mi++) \
    _Pragma("unroll") for (int ni = 0; ni < 4; ni++) \
    _Pragma("unroll") for (int r = 0; r < 4; r++) acc[mi][ni][r] = 0.f;

// 32x32 warp tile step: A [m][k] VKP (ldsm), B [k][n] SKP (ldsm.trans)
#define F16_STEP32_MKKN(At, Bt, wm, wn, j, r) \
    _Pragma("unroll") \
    for (int ks = 0; ks < 64; ks += 16) { \
        uint32_t af[2][4]; \
        _Pragma("unroll") \
        for (int mi = 0; mi < 2; mi++) { \
            int mrow = (wm) + mi * 16 + (((j) & 1) ? 8 : 0) + (r); \
            int ko = ks + (((j) & 2) ? 8 : 0); \
            ldsm4(af[mi][0], af[mi][1], af[mi][2], af[mi][3], \
                  smem_cast((At) + (size_t)mrow * VKP + ko)); \
        } \
        _Pragma("unroll") \
        for (int np = 0; np < 2; np++) { \
            int krow = ks + (((j) & 1) ? 8 : 0) + (r); \
            int no = (wn) + np * 16 + (((j) & 2) ? 8 : 0); \
            uint32_t b0, b1, b2, b3; \
            ldsm4t(b0, b1, b2, b3, smem_cast((Bt) + (size_t)krow * SKP + no)); \
            uint32_t bl[2] = { b0, b1 }, bh[2] = { b2, b3 }; \
            _Pragma("unroll") \
            for (int mi = 0; mi < 2; mi++) { \
                mma_f16(acc[mi][np * 2 + 0], af[mi], bl); \
                mma_f16(acc[mi][np * 2 + 1], af[mi], bh); \
            } \
        } \
    }

// 32x32 warp tile step: A [m][k] VKP, B [n][k] VKP (both ldsm)
#define F16_STEP32_MKNK(At, Bt, wm, wn, j, r) \
    _Pragma("unroll") \
    for (int ks = 0; ks < 64; ks += 16) { \
        uint32_t af[2][4]; \
        _Pragma("unroll") \
        for (int mi = 0; mi < 2; mi++) { \
            int mrow = (wm) + mi * 16 + (((j) & 1) ? 8 : 0) + (r); \
            int ko = ks + (((j) & 2) ? 8 : 0); \
            ldsm4(af[mi][0], af[mi][1], af[mi][2], af[mi][3], \
                  smem_cast((At) + (size_t)mrow * VKP + ko)); \
        } \
        _Pragma("unroll") \
        for (int np = 0; np < 2; np++) { \
            int nrow = (wn) + np * 16 + (((j) & 2) ? 8 : 0) + (r); \
            int ko = ks + (((j) & 1) ? 8 : 0); \
            uint32_t b0, b1, b2, b3; \
            ldsm4(b0, b1, b2, b3, smem_cast((Bt) + (size_t)nrow * VKP + ko)); \
            uint32_t bl[2] = { b0, b1 }, bh[2] = { b2, b3 }; \
            _Pragma("unroll") \
            for (int mi = 0; mi < 2; mi++) { \
                mma_f16(acc[mi][np * 2 + 0], af[mi], bl); \
                mma_f16(acc[mi][np * 2 + 1], af[mi], bh); \
            } \
        } \
    }

// ---- arg structs ----
struct Proj9 {
    const __half* X[9]; const __half* W[9]; const float* B[9];
    __half* DH[9]; int sidx[9];
};
struct Att3h {
    const __half* Q[3]; const __half* KS[3]; const __half* V[3]; __half* O[3];
};

// =====================================================================
// cvt kernels
// =====================================================================
__global__ void __launch_bounds__(256) cvt_x3(
    const float* __restrict__ x0, const float* __restrict__ x1,
    const float* __restrict__ x2,
    __half* __restrict__ d0, __half* __restrict__ d1, __half* __restrict__ d2)
{
    const float* src = (blockIdx.y == 0) ? x0 : (blockIdx.y == 1) ? x1 : x2;
    __half* dst      = (blockIdx.y == 0) ? d0 : (blockIdx.y == 1) ? d1 : d2;
    size_t i = ((size_t)blockIdx.x * 256 + threadIdx.x) * 4;
    float4 v = *(const float4*)(src + i);
    *(__half2*)(dst + i)     = __floats2half2_rn(v.x, v.y);
    *(__half2*)(dst + i + 2) = __floats2half2_rn(v.z, v.w);
}

struct W11 { const float* src[11]; };
__global__ void __launch_bounds__(256) cvt_w11(W11 W, __half* __restrict__ base)
{
    const float* src = W.src[blockIdx.y];
    __half* dst = base + (size_t)blockIdx.y * Cdim * Cdim;
    size_t i = ((size_t)blockIdx.x * 256 + threadIdx.x) * 4;
    float4 v = *(const float4*)(src + i);
    *(__half2*)(dst + i)     = __floats2half2_rn(v.x, v.y);
    *(__half2*)(dst + i + 2) = __floats2half2_rn(v.z, v.w);
}

// =====================================================================
// proj fp16, BM=64: dst[o][n] = scale*(W X + b). grid (18, 4, 36)
// =====================================================================
#define PJ_SMEM (2*64*VKP*2 + 2*64*SKP*2)   // 53248 B

__global__ void __launch_bounds__(256, 2) proj_h9(Proj9 P, const float* __restrict__ s)
{
    extern __shared__ __half hsm[];
    __half* Ab = hsm;                     // [2][64][VKP]
    __half* Bb = hsm + 2 * 64 * VKP;      // [2][64][SKP]

    const int z = blockIdx.z, job = z >> 2, b = z & 3;
    const int o0 = blockIdx.y * 64;
    const int n0 = blockIdx.x * BN;
    const int tid = threadIdx.x;
    const int warp = tid >> 5, lane = tid & 31;
    const int g = lane >> 2, t = lane & 3;
    const int j = lane >> 3, r = lane & 7;
    const int wm = (warp & 1) * 32, wn = (warp >> 1) * 32;

    const __half* Xb   = P.X[job] + (size_t)b * CN;
    const __half* Wt   = P.W[job];
    const float*  bias = P.B[job];
    __half* dsth = P.DH[job] + (size_t)b * CN;
    const int sidx = P.sidx[job];

    const int u = tid & 127;
    const bool isB = (tid >= 128);
    const int r0a = u >> 3, cca = u & 7;
    const int r0b = u >> 4, ccb = u & 15;

    auto prefetch = [&](int bufp, int k0) {
        if (!isB) {
#pragma unroll
            for (int p = 0; p < 4; p++) {
                int row = r0a + 16 * p;
                const __half* gp = Wt + (size_t)(o0 + row) * Cdim + k0 + cca * 8;
                __half* sp = Ab + ((size_t)bufp * 64 + row) * VKP + cca * 8;
                CP_ASYNC16(smem_cast(sp), gp);
            }
        } else {
#pragma unroll
            for (int p = 0; p < 8; p++) {
                int row = r0b + 8 * p;
                const __half* gp = Xb + (size_t)(k0 + row) * Ndim + n0 + ccb * 8;
                __half* sp = Bb + ((size_t)bufp * 64 + row) * SKP + ccb * 8;
                CP_ASYNC16(smem_cast(sp), gp);
            }
        }
        CP_COMMIT();
    };

    DECL_ACC2;

    prefetch(0, 0);
    prefetch(1, 64);
    const int NIT = Cdim / 64;   // 4
    for (int it = 0; it < NIT; it++) {
        int buf = it & 1;
        if (it == NIT - 1) CP_WAIT0(); else CP_WAIT1();
        __syncthreads();
        const __half* At = Ab + (size_t)buf * 64 * VKP;
        const __half* Bt = Bb + (size_t)buf * 64 * SKP;
        F16_STEP32_MKKN(At, Bt, wm, wn, j, r);
        __syncthreads();
        if (it + 2 < NIT) prefetch(buf, (it + 2) * 64);
    }

    const float scale = (sidx >= 0) ? s[sidx] : 1.f;
#pragma unroll
    for (int mi = 0; mi < 2; mi++)
#pragma unroll
        for (int r2 = 0; r2 < 2; r2++) {
            int m = o0 + wm + mi * 16 + g + r2 * 8;
            float bi = bias[m];
#pragma unroll
            for (int ni = 0; ni < 4; ni++) {
                int n = n0 + wn + ni * 8 + t * 2;
                size_t idx = (size_t)m * Ndim + n;
                float v0 = (acc[mi][ni][r2 * 2 + 0] + bi) * scale;
                float v1 = (acc[mi][ni][r2 * 2 + 1] + bi) * scale;
                *(__half2*)(dsth + idx) = __floats2half2_rn(v0, v1);
            }
        }
}

// =====================================================================
// ksum3 (fp16 in): KS[a] = fp16(float(Ka)+float(Kb))
// =====================================================================
__global__ void __launch_bounds__(256) ksum3_kernel(
    const __half* __restrict__ K0, const __half* __restrict__ K1,
    const __half* __restrict__ K2,
    __half* __restrict__ S0, __half* __restrict__ S1, __half* __restrict__ S2)
{
    size_t i = ((size_t)blockIdx.x * 256 + threadIdx.x) * 4;
#pragma unroll
    for (int h = 0; h < 2; h++) {
        float2 a = __half22float2(*(const __half2*)(K0 + i + h * 2));
        float2 b = __half22float2(*(const __half2*)(K1 + i + h * 2));
        float2 c = __half22float2(*(const __half2*)(K2 + i + h * 2));
        *(__half2*)(S0 + i + h * 2) = __floats2half2_rn(c.x + b.x, c.y + b.y);
        *(__half2*)(S1 + i + h * 2) = __floats2half2_rn(a.x + b.x, a.y + b.y);
        *(__half2*)(S2 + i + h * 2) = __floats2half2_rn(a.x + c.x, a.y + c.y);
    }
}

// =====================================================================
// scores fp16 (unchanged from R12): S = (1/16) Q^T KS
// =====================================================================
#define SC_SMEM (2 * 2 * 64 * SKP * 2)   // 69632 B

__global__ void __launch_bounds__(256, 2) scores_h(Att3h A)
{
    extern __shared__ __half hsm[];
    __half* Ab = hsm;
    __half* Bb = hsm + 2 * 64 * SKP;

    const int z = blockIdx.z, a = z >> 2, b = z & 3;
    const int y0 = blockIdx.y * 128;
    const int z0 = blockIdx.x * BN;
    const int tid = threadIdx.x;
    const int warp = tid >> 5, lane = tid & 31;
    const int t = lane & 3;
    const int wm = (warp & 1) * 64, wn = (warp >> 1) * 32;
    const __half* Qb = A.Q[a]  + (size_t)b * CN;
    const __half* Kb = A.KS[a] + (size_t)b * CN;

    const int u  = tid & 127;
    const int r0 = u >> 4;
    const int cc = u & 15;
    const bool isB = (tid >= 128);
    const __half* gsrc = isB ? (Kb + z0) : (Qb + y0);
    __half* sbase = isB ? Bb : Ab;

    auto prefetch = [&](int bufp, int k0) {
#pragma unroll
        for (int p = 0; p < 8; p++) {
            int row = r0 + 8 * p;
            const __half* gp = gsrc + (size_t)(k0 + row) * Ndim + cc * 8;
            __half* sp = sbase + ((size_t)bufp * 64 + row) * SKP + cc * 8;
            CP_ASYNC16(smem_cast(sp), gp);
        }
        CP_COMMIT();
    };

    DECL_ACC4;

    prefetch(0, 0);
    prefetch(1, 64);
    const int NIT = Cdim / 64;   // 4
    for (int it = 0; it < NIT; it++) {
        int buf = it & 1;
        if (it == NIT - 1) CP_WAIT0(); else CP_WAIT1();
        __syncthreads();
        const __half* At = Ab + (size_t)buf * 64 * SKP;
        const __half* Bt = Bb + (size_t)buf * 64 * SKP;
        const int j = lane >> 3, r = lane & 7;
#pragma unroll
        for (int ks = 0; ks < 64; ks += 16) {
            uint32_t af[4][4];
#pragma unroll
            for (int mi = 0; mi < 4; mi++) {
                int krow = ks + ((j & 2) ? 8 : 0) + r;
                int mo = wm + mi * 16 + ((j & 1) ? 8 : 0);
                ldsm4t(af[mi][0], af[mi][1], af[mi][2], af[mi][3],
                       smem_cast(At + (size_t)krow * SKP + mo));
            }
#pragma unroll
            for (int np = 0; np < 2; np++) {
                int krow = ks + ((j & 1) ? 8 : 0) + r;
                int no = wn + np * 16 + ((j & 2) ? 8 : 0);
                uint32_t b0, b1, b2, b3;
                ldsm4t(b0, b1, b2, b3, smem_cast(Bt + (size_t)krow * SKP + no));
                uint32_t bl[2] = { b0, b1 }, bh[2] = { b2, b3 };
#pragma unroll
                for (int mi = 0; mi < 4; mi++) {
                    mma_f16(acc[mi][np * 2 + 0], af[mi], bl);
                    mma_f16(acc[mi][np * 2 + 1], af[mi], bh);
                }
            }
        }
        __syncthreads();
        if (it + 2 < NIT) prefetch(buf, (it + 2) * 64);
    }

    __half* Sb = g_S3h + (size_t)z * NN;
    const int g = lane >> 2;
#pragma unroll
    for (int mi = 0; mi < 4; mi++)
#pragma unroll
        for (int r2 = 0; r2 < 2; r2++) {
            int y = y0 + wm + mi * 16 + g + r2 * 8;
#pragma unroll
            for (int ni = 0; ni < 4; ni++) {
                int zz = z0 + wn + ni * 8 + t * 2;
                size_t idx = (size_t)y * Ndim + zz;
                *(__half2*)(Sb + idx) = __floats2half2_rn(
                    acc[mi][ni][r2 * 2 + 0] * 0.0625f,
                    acc[mi][ni][r2 * 2 + 1] * 0.0625f);
            }
        }
}

// =====================================================================
// softmax: 2 rows per 256-thread block, half2 I/O
// =====================================================================
__global__ void __launch_bounds__(256) softmax_kernel()
{
    const int sub = threadIdx.x >> 7;
    const size_t row = (size_t)blockIdx.x * 2 + sub;
    __half2* p = (__half2*)(g_S3h + row * Ndim);
    const int t = threadIdx.x & 127;
    const int warp = threadIdx.x >> 5, lane = threadIdx.x & 31;
    __shared__ float redm[8], reds[8];

    float2 v[9];
#pragma unroll
    for (int i = 0; i < 9; i++) v[i] = __half22float2(p[t + i * 128]);

    float mx = fmaxf(v[0].x, v[0].y);
#pragma unroll
    for (int i = 1; i < 9; i++) mx = fmaxf(mx, fmaxf(v[i].x, v[i].y));
#pragma unroll
    for (int off = 16; off > 0; off >>= 1)
        mx = fmaxf(mx, __shfl_xor_sync(0xffffffffu, mx, off));
    if (lane == 0) redm[warp] = mx;
    __syncthreads();
    {
        int base = sub * 4;
        mx = fmaxf(fmaxf(redm[base], redm[base + 1]),
                   fmaxf(redm[base + 2], redm[base + 3]));
    }

    float sum = 0.f;
#pragma unroll
    for (int i = 0; i < 9; i++) {
        v[i].x = __expf(v[i].x - mx);
        v[i].y = __expf(v[i].y - mx);
        sum += v[i].x + v[i].y;
    }
#pragma unroll
    for (int off = 16; off > 0; off >>= 1)
        sum += __shfl_xor_sync(0xffffffffu, sum, off);
    if (lane == 0) reds[warp] = sum;
    __syncthreads();
    float inv;
    {
        int base = sub * 4;
        inv = 1.f / (reds[base] + reds[base + 1] + reds[base + 2] + reds[base + 3]);
    }
#pragma unroll
    for (int i = 0; i < 9; i++)
        p[t + i * 128] = __floats2half2_rn(v[i].x * inv, v[i].y * inv);
}

// =====================================================================
// AV fp16, BM=64: dst[c][n] = sum_m V[c][m] P[n][m]. grid (18, 4, 12)
// =====================================================================
#define AV_SMEM (2*64*VKP*2 + 2*128*VKP*2)   // 55296 B

__global__ void __launch_bounds__(256, 2) av_h(Att3h A)
{
    extern __shared__ __half hsm[];
    __half* Ab = hsm;                     // [2][64][VKP]
    __half* Bb = hsm + 2 * 64 * VKP;      // [2][128][VKP]

    const int z = blockIdx.z, a = z >> 2, b = z & 3;
    const int c0 = blockIdx.y * 64;
    const int n0 = blockIdx.x * BN;
    const int tid = threadIdx.x;
    const int warp = tid >> 5, lane = tid & 31;
    const int t = lane & 3;
    const int j = lane >> 3, r = lane & 7;
    const int wm = (warp & 1) * 32, wn = (warp >> 1) * 32;
    const __half* Vb = A.V[a] + (size_t)b * CN;
    const __half* Pb = g_S3h + (size_t)z * NN;
    __half*      dst = A.O[a] + (size_t)b * CN;

    const int u  = tid & 127;
    const int r0 = u >> 3;
    const int cc = u & 7;
    const bool isB = (tid >= 128);

    auto prefetch = [&](int bufp, int k0) {
        if (!isB) {
#pragma unroll
            for (int p = 0; p < 4; p++) {
                int row = r0 + 16 * p;
                const __half* gp = Vb + (size_t)(c0 + row) * Ndim + k0 + cc * 8;
                __half* sp = Ab + ((size_t)bufp * 64 + row) * VKP + cc * 8;
                CP_ASYNC16(smem_cast(sp), gp);
            }
        } else {
#pragma unroll
            for (int p = 0; p < 8; p++) {
                int row = r0 + 16 * p;
                const __half* gp = Pb + (size_t)(n0 + row) * Ndim + k0 + cc * 8;
                __half* sp = Bb + ((size_t)bufp * 128 + row) * VKP + cc * 8;
                CP_ASYNC16(smem_cast(sp), gp);
            }
        }
        CP_COMMIT();
    };

    DECL_ACC2;

    prefetch(0, 0);
    prefetch(1, 64);
    const int NIT = Ndim / 64;   // 36
    for (int it = 0; it < NIT; it++) {
        int buf = it & 1;
        if (it == NIT - 1) CP_WAIT0(); else CP_WAIT1();
        __syncthreads();
        const __half* At = Ab + (size_t)buf * 64 * VKP;
        const __half* Bt = Bb + (size_t)buf * 128 * VKP;
        F16_STEP32_MKNK(At, Bt, wm, wn, j, r);
        __syncthreads();
        if (it + 2 < NIT) prefetch(buf, (it + 2) * 64);
    }

    const int g = lane >> 2;
#pragma unroll
    for (int mi = 0; mi < 2; mi++)
#pragma unroll
        for (int r2 = 0; r2 < 2; r2++) {
            int c = c0 + wm + mi * 16 + g + r2 * 8;
#pragma unroll
            for (int ni = 0; ni < 4; ni++) {
                int n = n0 + wn + ni * 8 + t * 2;
                *(__half2*)(dst + (size_t)c * Ndim + n) = __floats2half2_rn(
                    acc[mi][ni][r2 * 2 + 0], acc[mi][ni][r2 * 2 + 1]);
            }
        }
}

// =====================================================================
// gate fp16, BM=64: F = sigmoid(Wg X + bg) * X. grid (18, 4, 12)
// =====================================================================
__global__ void __launch_bounds__(256, 2) gate_h3(
    const __half* __restrict__ WgH, const float* __restrict__ bg)
{
    extern __shared__ __half hsm[];
    __half* Ab = hsm;                     // [2][64][VKP]
    __half* Bb = hsm + 2 * 64 * VKP;      // [2][64][SKP]

    const int z = blockIdx.z, a = z >> 2, b = z & 3;
    const int o0 = blockIdx.y * 64;
    const int n0 = blockIdx.x * BN;
    const int tid = threadIdx.x;
    const int warp = tid >> 5, lane = tid & 31;
    const int g = lane >> 2, t = lane & 3;
    const int jj = lane >> 3, rr = lane & 7;
    const int wm = (warp & 1) * 32, wn = (warp >> 1) * 32;
    const __half* Xb = g_Wh[a] + (size_t)b * CN;
    __half*      F  = g_F3h[a] + (size_t)b * CN;

    const int u = tid & 127;
    const bool isB = (tid >= 128);
    const int r0a = u >> 3, cca = u & 7;
    const int r0b = u >> 4, ccb = u & 15;

    auto prefetch = [&](int bufp, int k0) {
        if (!isB) {
#pragma unroll
            for (int p = 0; p < 4; p++) {
                int row = r0a + 16 * p;
                const __half* gp = WgH + (size_t)(o0 + row) * Cdim + k0 + cca * 8;
                __half* sp = Ab + ((size_t)bufp * 64 + row) * VKP + cca * 8;
                CP_ASYNC16(smem_cast(sp), gp);
            }
        } else {
#pragma unroll
            for (int p = 0; p < 8; p++) {
                int row = r0b + 8 * p;
                const __half* gp = Xb + (size_t)(k0 + row) * Ndim + n0 + ccb * 8;
                __half* sp = Bb + ((size_t)bufp * 64 + row) * SKP + ccb * 8;
                CP_ASYNC16(smem_cast(sp), gp);
            }
        }
        CP_COMMIT();
    };

    DECL_ACC2;

    prefetch(0, 0);
    prefetch(1, 64);
    const int NIT = Cdim / 64;   // 4
    for (int it = 0; it < NIT; it++) {
        int buf = it & 1;
        if (it == NIT - 1) CP_WAIT0(); else CP_WAIT1();
        __syncthreads();
        const __half* At = Ab + (size_t)buf * 64 * VKP;
        const __half* Bt = Bb + (size_t)buf * 64 * SKP;
        F16_STEP32_MKKN(At, Bt, wm, wn, jj, rr);
        __syncthreads();
        if (it + 2 < NIT) prefetch(buf, (it + 2) * 64);
    }

#pragma unroll
    for (int mi = 0; mi < 2; mi++)
#pragma unroll
        for (int r2 = 0; r2 < 2; r2++) {
            int o = o0 + wm + mi * 16 + g + r2 * 8;
            float bi = bg[o];
#pragma unroll
            for (int ni = 0; ni < 4; ni++) {
                int n = n0 + wn + ni * 8 + t * 2;
                size_t idx = (size_t)o * Ndim + n;
                __half2 xh = *(const __half2*)(Xb + idx);
                float x0 = __low2float(xh), x1 = __high2float(xh);
                float g0 = acc[mi][ni][r2 * 2 + 0] + bi;
                float g1 = acc[mi][ni][r2 * 2 + 1] + bi;
                *(__half2*)(F + idx) = __floats2half2_rn(
                    x0 / (1.f + __expf(-g0)),
                    x1 / (1.f + __expf(-g1)));
            }
        }
}

// =====================================================================
// final fp16, BM=64: out = WoH @ (F0+F1+F2) + bo. grid (18, 4, 4)
// =====================================================================
__global__ void __launch_bounds__(256, 2) final_h(
    const __half* __restrict__ WoH, const float* __restrict__ bo,
    float* __restrict__ out)
{
    extern __shared__ __half hsm[];
    __half* Ab = hsm;                     // [2][64][VKP]
    __half* Bb = hsm + 2 * 64 * VKP;      // [2][64][SKP]

    const int b  = blockIdx.z;
    const int o0 = blockIdx.y * 64;
    const int n0 = blockIdx.x * BN;
    const int tid = threadIdx.x;
    const int warp = tid >> 5, lane = tid & 31;
    const int g = lane >> 2, t = lane & 3;
    const int jj = lane >> 3, rr = lane & 7;
    const int wm = (warp & 1) * 32, wn = (warp >> 1) * 32;
    const __half* F0 = g_F3h[0] + (size_t)b * CN;
    const __half* F1 = g_F3h[1] + (size_t)b * CN;
    const __half* F2 = g_F3h[2] + (size_t)b * CN;
    float* dst = out + (size_t)b * CN;

    const int u = tid & 127;
    const bool isB = (tid >= 128);
    const int r0a = u >> 3, cca = u & 7;
    const int r0b = u >> 4, ccb = u & 15;

    auto prefetchA = [&](int bufp, int k0) {
        if (!isB) {
#pragma unroll
            for (int p = 0; p < 4; p++) {
                int row = r0a + 16 * p;
                const __half* gp = WoH + (size_t)(o0 + row) * Cdim + k0 + cca * 8;
                __half* sp = Ab + ((size_t)bufp * 64 + row) * VKP + cca * 8;
                CP_ASYNC16(smem_cast(sp), gp);
            }
        }
        CP_COMMIT();
    };

    __half2 breg[8][4];
    auto loadB = [&](int k0) {
        if (isB) {
#pragma unroll
            for (int p = 0; p < 8; p++) {
                int row = r0b + 8 * p;
                size_t off = (size_t)(k0 + row) * Ndim + n0 + ccb * 8;
#pragma unroll
                for (int c = 0; c < 4; c++) {
                    float2 a0 = __half22float2(*(const __half2*)(F0 + off + c * 2));
                    float2 a1 = __half22float2(*(const __half2*)(F1 + off + c * 2));
                    float2 a2 = __half22float2(*(const __half2*)(F2 + off + c * 2));
                    breg[p][c] = __floats2half2_rn(a0.x + a1.x + a2.x,
                                                   a0.y + a1.y + a2.y);
                }
            }
        }
    };
    auto storeB = [&](int bufp) {
        if (isB) {
#pragma unroll
            for (int p = 0; p < 8; p++) {
                int row = r0b + 8 * p;
                __half2* sp = (__half2*)(Bb + ((size_t)bufp * 64 + row) * SKP + ccb * 8);
#pragma unroll
                for (int c = 0; c < 4; c++) sp[c] = breg[p][c];
            }
        }
    };

    DECL_ACC2;

    prefetchA(0, 0);
    prefetchA(1, 64);
    loadB(0); storeB(0);
    loadB(64);
    const int NIT = Cdim / 64;   // 4
    for (int it = 0; it < NIT; it++) {
        int buf = it & 1;
        if (it == NIT - 1) CP_WAIT0(); else CP_WAIT1();
        __syncthreads();
        const __half* At = Ab + (size_t)buf * 64 * VKP;
        const __half* Bt = Bb + (size_t)buf * 64 * SKP;
        F16_STEP32_MKKN(At, Bt, wm, wn, jj, rr);
        __syncthreads();
        if (it + 2 < NIT) prefetchA(buf, (it + 2) * 64);
        if (it + 1 < NIT) storeB(buf ^ 1);
        if (it + 2 < NIT) loadB((it + 2) * 64);
    }

#pragma unroll
    for (int mi = 0; mi < 2; mi++)
#pragma unroll
        for (int r2 = 0; r2 < 2; r2++) {
            int o = o0 + wm + mi * 16 + g + r2 * 8;
            float bi = bo[o];
#pragma unroll
            for (int ni = 0; ni < 4; ni++) {
                int n = n0 + wn + ni * 8 + t * 2;
                size_t idx = (size_t)o * Ndim + n;
                float2 v = { acc[mi][ni][r2 * 2 + 0] + bi,
                             acc[mi][ni][r2 * 2 + 1] + bi };
                *(float2*)(dst + idx) = v;
            }
        }
}

// =====================================================================
// launch
// =====================================================================
extern "C" void kernel_launch(void* const* d_in, const int* in_sizes, int n_in,
                              void* d_out, int out_size)
{
    const float* x[3] = { (const float*)d_in[0], (const float*)d_in[1], (const float*)d_in[2] };
    const float* s = (const float*)d_in[3];
    const float *wq[3], *bq[3], *wk[3], *bk[3], *wv[3], *bv[3];
    for (int m = 0; m < 3; m++) {
        wq[m] = (const float*)d_in[4 + 6 * m];
        bq[m] = (const float*)d_in[5 + 6 * m];
        wk[m] = (const float*)d_in[6 + 6 * m];
        bk[m] = (const float*)d_in[7 + 6 * m];
        wv[m] = (const float*)d_in[8 + 6 * m];
        bv[m] = (const float*)d_in[9 + 6 * m];
    }
    const float* wg = (const float*)d_in[22];
    const float* bg = (const float*)d_in[23];
    const float* wo = (const float*)d_in[24];
    const float* bo = (const float*)d_in[25];
    float* out = (float*)d_out;

    __half *gH, *gXh, *gWT, *gWh, *gKh;
    cudaGetSymbolAddress((void**)&gH,  g_H);
    cudaGetSymbolAddress((void**)&gXh, g_Xh);
    cudaGetSymbolAddress((void**)&gWT, g_WT);
    cudaGetSymbolAddress((void**)&gWh, g_Wh);
    cudaGetSymbolAddress((void**)&gKh, g_Kh);

    __half *Kh[3], *Qh[3], *KSh[3], *Vh[3], *Xh[3], *Wout[3];
    for (int m = 0; m < 3; m++) {
        Kh[m]  = gKh + (size_t)m * PLANE;
        Qh[m]  = gH + (size_t)(0 + m) * PLANE;
        KSh[m] = gH + (size_t)(3 + m) * PLANE;
        Vh[m]  = gH + (size_t)(6 + m) * PLANE;
        Xh[m]  = gXh + (size_t)m * PLANE;
        Wout[m] = gWh + (size_t)m * PLANE;
    }
    __half* WqH[3]; __half* WkH[3]; __half* WvH[3];
    for (int m = 0; m < 3; m++) {
        WqH[m] = gWT + (size_t)(3 * m + 0) * Cdim * Cdim;
        WkH[m] = gWT + (size_t)(3 * m + 1) * Cdim * Cdim;
        WvH[m] = gWT + (size_t)(3 * m + 2) * Cdim * Cdim;
    }
    __half* WgH = gWT + (size_t)9 * Cdim * Cdim;
    __half* WoH = gWT + (size_t)10 * Cdim * Cdim;

    W11 WC;
    for (int m = 0; m < 3; m++) {
        WC.src[3 * m + 0] = wq[m];
        WC.src[3 * m + 1] = wk[m];
        WC.src[3 * m + 2] = wv[m];
    }
    WC.src[9]  = wg;
    WC.src[10] = wo;

    Proj9 P;
    for (int m = 0; m < 3; m++) {
        P.X[3 * m + 0] = Xh[m]; P.W[3 * m + 0] = WqH[m]; P.B[3 * m + 0] = bq[m];
        P.DH[3 * m + 0] = Qh[m]; P.sidx[3 * m + 0] = m;
        P.X[3 * m + 1] = Xh[m]; P.W[3 * m + 1] = WkH[m]; P.B[3 * m + 1] = bk[m];
        P.DH[3 * m + 1] = Kh[m]; P.sidx[3 * m + 1] = m;
        P.X[3 * m + 2] = Xh[m]; P.W[3 * m + 2] = WvH[m]; P.B[3 * m + 2] = bv[m];
        P.DH[3 * m + 2] = Vh[m]; P.sidx[3 * m + 2] = -1;
    }

    // attends: w_rgb(Q0; K2+K1; V0), w_depth(Q2; K0+K1; V2), w_thermal(Q1; K0+K2; V1)
    Att3h A;
    const int qi[3] = { 0, 2, 1 };
    for (int a = 0; a < 3; a++) {
        A.Q[a]  = Qh[qi[a]];
        A.KS[a] = KSh[a];
        A.V[a]  = Vh[qi[a]];
        A.O[a]  = Wout[a];
    }

    cudaFuncSetAttribute(proj_h9,  cudaFuncAttributeMaxDynamicSharedMemorySize, PJ_SMEM);
    cudaFuncSetAttribute(scores_h, cudaFuncAttributeMaxDynamicSharedMemorySize, SC_SMEM);
    cudaFuncSetAttribute(av_h,     cudaFuncAttributeMaxDynamicSharedMemorySize, AV_SMEM);
    cudaFuncSetAttribute(gate_h3,  cudaFuncAttributeMaxDynamicSharedMemorySize, PJ_SMEM);
    cudaFuncSetAttribute(final_h,  cudaFuncAttributeMaxDynamicSharedMemorySize, PJ_SMEM);

    dim3 blk(256);
    cvt_x3 <<<dim3(PLANE / 1024, 3), blk>>>(x[0], x[1], x[2], Xh[0], Xh[1], Xh[2]);
    cvt_w11<<<dim3(Cdim * Cdim / 1024, 11), blk>>>(WC, gWT);
    proj_h9<<<dim3(Ndim / BN, Cdim / 64, 36), blk, PJ_SMEM>>>(P, s);
    ksum3_kernel<<<dim3(PLANE / 1024), blk>>>(Kh[0], Kh[1], Kh[2], KSh[0], KSh[1], KSh[2]);
    scores_h<<<dim3(Ndim / BN, Ndim / 128, 12), blk, SC_SMEM>>>(A);
    softmax_kernel<<<dim3(3 * Bdim * Ndim / 2), blk>>>();
    av_h   <<<dim3(Ndim / BN, Cdim / 64, 12), blk, AV_SMEM>>>(A);
    gate_h3<<<dim3(Ndim / BN, Cdim / 64, 12), blk, PJ_SMEM>>>(WgH, bg);
    final_h<<<dim3(Ndim / BN, Cdim / 64, 4), blk, PJ_SMEM>>>(WoH, bo, out);
}

// round 14
// speedup vs baseline: 1.0405x; 1.0405x over previous
#include <cuda_runtime.h>
#include <cuda_fp16.h>
#include <cstdint>
#include <math.h>

#define Bdim 4
#define Cdim 256
#define Ndim 2304      // 48*48
#define PLANE (Bdim*Cdim*Ndim)
#define CN   (Cdim*Ndim)
#define NN   ((size_t)Ndim*Ndim)

#define BM 128
#define BN 128
#define SKP 136        // fp16 [k][*] stride (272B)
#define VKP 72         // fp16 [row][k] stride (144B)

// ---- scratch ----
__device__ __half g_Xh[3][PLANE];                    // fp16 inputs
__device__ __half g_WT[11][Cdim * Cdim];             // fp16 weights
__device__ __half g_Kh[3][PLANE];                    // raw fp16 K
__device__ __half g_H[9][PLANE];                     // Q0..2, KS0..2, V0..2
__device__ __half g_S3h[(size_t)3 * Bdim * NN];      // scores / probs
__device__ __half g_Wh[3][PLANE];                    // attention outputs
__device__ __half g_F3h[3][PLANE];                   // gated outputs

// ---- fp16 mma + ldmatrix ----
__device__ __forceinline__ void mma_f16(float c[4], const uint32_t a[4], const uint32_t b[2]) {
    asm volatile(
        "mma.sync.aligned.m16n8k16.row.col.f32.f16.f16.f32 "
        "{%0,%1,%2,%3}, {%4,%5,%6,%7}, {%8,%9}, {%0,%1,%2,%3};"
        : "+f"(c[0]), "+f"(c[1]), "+f"(c[2]), "+f"(c[3])
        : "r"(a[0]), "r"(a[1]), "r"(a[2]), "r"(a[3]), "r"(b[0]), "r"(b[1]));
}
__device__ __forceinline__ void ldsm4(uint32_t& r0, uint32_t& r1, uint32_t& r2, uint32_t& r3, uint32_t a) {
    asm volatile("ldmatrix.sync.aligned.m8n8.x4.shared.b16 {%0,%1,%2,%3}, [%4];"
        : "=r"(r0), "=r"(r1), "=r"(r2), "=r"(r3) : "r"(a));
}
__device__ __forceinline__ void ldsm4t(uint32_t& r0, uint32_t& r1, uint32_t& r2, uint32_t& r3, uint32_t a) {
    asm volatile("ldmatrix.sync.aligned.m8n8.x4.trans.shared.b16 {%0,%1,%2,%3}, [%4];"
        : "=r"(r0), "=r"(r1), "=r"(r2), "=r"(r3) : "r"(a));
}

// ---- cp.async ----
__device__ __forceinline__ uint32_t smem_cast(const void* p) {
    return (uint32_t)__cvta_generic_to_shared(p);
}
#define CP_ASYNC16(dst_u32, gptr) \
    asm volatile("cp.async.cg.shared.global [%0], [%1], 16;" :: "r"(dst_u32), "l"(gptr))
#define CP_COMMIT() asm volatile("cp.async.commit_group;" ::: "memory")
#define CP_WAIT1()  asm volatile("cp.async.wait_group 1;" ::: "memory")
#define CP_WAIT0()  asm volatile("cp.async.wait_group 0;" ::: "memory")

#define DECL_ACC float acc[4][4][4]; \
    _Pragma("unroll") for (int mi = 0; mi < 4; mi++) \
    _Pragma("unroll") for (int ni = 0; ni < 4; ni++) \
    _Pragma("unroll") for (int r = 0; r < 4; r++) acc[mi][ni][r] = 0.f;

// fp16 GEMM inner step: A [m][k] VKP (ldsm), B [k][n] SKP (ldsm.trans); 64x32 warp tile
#define F16_STEP_MKKN(At, Bt, wm, wn, j, r) \
    _Pragma("unroll") \
    for (int ks = 0; ks < 64; ks += 16) { \
        uint32_t af[4][4]; \
        _Pragma("unroll") \
        for (int mi = 0; mi < 4; mi++) { \
            int mrow = (wm) + mi * 16 + (((j) & 1) ? 8 : 0) + (r); \
            int ko = ks + (((j) & 2) ? 8 : 0); \
            ldsm4(af[mi][0], af[mi][1], af[mi][2], af[mi][3], \
                  smem_cast((At) + (size_t)mrow * VKP + ko)); \
        } \
        _Pragma("unroll") \
        for (int np = 0; np < 2; np++) { \
            int krow = ks + (((j) & 1) ? 8 : 0) + (r); \
            int no = (wn) + np * 16 + (((j) & 2) ? 8 : 0); \
            uint32_t b0, b1, b2, b3; \
            ldsm4t(b0, b1, b2, b3, smem_cast((Bt) + (size_t)krow * SKP + no)); \
            uint32_t bl[2] = { b0, b1 }, bh[2] = { b2, b3 }; \
            _Pragma("unroll") \
            for (int mi = 0; mi < 4; mi++) { \
                mma_f16(acc[mi][np * 2 + 0], af[mi], bl); \
                mma_f16(acc[mi][np * 2 + 1], af[mi], bh); \
            } \
        } \
    }

// fp16 GEMM inner step: A [m][k] VKP, B [n][k] VKP (both ldsm); 64x32 warp tile
#define F16_STEP_MKNK(At, Bt, wm, wn, j, r) \
    _Pragma("unroll") \
    for (int ks = 0; ks < 64; ks += 16) { \
        uint32_t af[4][4]; \
        _Pragma("unroll") \
        for (int mi = 0; mi < 4; mi++) { \
            int mrow = (wm) + mi * 16 + (((j) & 1) ? 8 : 0) + (r); \
            int ko = ks + (((j) & 2) ? 8 : 0); \
            ldsm4(af[mi][0], af[mi][1], af[mi][2], af[mi][3], \
                  smem_cast((At) + (size_t)mrow * VKP + ko)); \
        } \
        _Pragma("unroll") \
        for (int np = 0; np < 2; np++) { \
            int nrow = (wn) + np * 16 + (((j) & 2) ? 8 : 0) + (r); \
            int ko = ks + (((j) & 1) ? 8 : 0); \
            uint32_t b0, b1, b2, b3; \
            ldsm4(b0, b1, b2, b3, smem_cast((Bt) + (size_t)nrow * VKP + ko)); \
            uint32_t bl[2] = { b0, b1 }, bh[2] = { b2, b3 }; \
            _Pragma("unroll") \
            for (int mi = 0; mi < 4; mi++) { \
                mma_f16(acc[mi][np * 2 + 0], af[mi], bl); \
                mma_f16(acc[mi][np * 2 + 1], af[mi], bh); \
            } \
        } \
    }

// ---- arg structs ----
struct Proj9 {
    const __half* X[9]; const __half* W[9]; const float* B[9];
    __half* DH[9]; int sidx[9];
};
struct Att3h {
    const __half* Q[3]; const __half* KS[3]; const __half* V[3]; __half* O[3];
};

// =====================================================================
// cvt kernels
// =====================================================================
__global__ void __launch_bounds__(256) cvt_x3(
    const float* __restrict__ x0, const float* __restrict__ x1,
    const float* __restrict__ x2,
    __half* __restrict__ d0, __half* __restrict__ d1, __half* __restrict__ d2)
{
    const float* src = (blockIdx.y == 0) ? x0 : (blockIdx.y == 1) ? x1 : x2;
    __half* dst      = (blockIdx.y == 0) ? d0 : (blockIdx.y == 1) ? d1 : d2;
    size_t i = ((size_t)blockIdx.x * 256 + threadIdx.x) * 4;
    float4 v = *(const float4*)(src + i);
    *(__half2*)(dst + i)     = __floats2half2_rn(v.x, v.y);
    *(__half2*)(dst + i + 2) = __floats2half2_rn(v.z, v.w);
}

struct W11 { const float* src[11]; };
__global__ void __launch_bounds__(256) cvt_w11(W11 W, __half* __restrict__ base)
{
    const float* src = W.src[blockIdx.y];
    __half* dst = base + (size_t)blockIdx.y * Cdim * Cdim;
    size_t i = ((size_t)blockIdx.x * 256 + threadIdx.x) * 4;
    float4 v = *(const float4*)(src + i);
    *(__half2*)(dst + i)     = __floats2half2_rn(v.x, v.y);
    *(__half2*)(dst + i + 2) = __floats2half2_rn(v.z, v.w);
}

// =====================================================================
// proj fp16 (R12 form, fp16 out incl. K): grid (18, 2, 36)
// =====================================================================
#define PJ_SMEM (2*128*VKP*2 + 2*64*SKP*2)   // 71680 B

__global__ void __launch_bounds__(256, 2) proj_h9(Proj9 P, const float* __restrict__ s)
{
    extern __shared__ __half hsm[];
    __half* Ab = hsm;                     // [2][128][VKP]
    __half* Bb = hsm + 2 * 128 * VKP;     // [2][64][SKP]

    const int z = blockIdx.z, job = z >> 2, b = z & 3;
    const int o0 = blockIdx.y * BM;
    const int n0 = blockIdx.x * BN;
    const int tid = threadIdx.x;
    const int warp = tid >> 5, lane = tid & 31;
    const int g = lane >> 2, t = lane & 3;
    const int j = lane >> 3, r = lane & 7;
    const int wm = (warp & 1) * 64, wn = (warp >> 1) * 32;

    const __half* Xb   = P.X[job] + (size_t)b * CN;
    const __half* Wt   = P.W[job];
    const float*  bias = P.B[job];
    __half* dsth = P.DH[job] + (size_t)b * CN;
    const int sidx = P.sidx[job];

    const int u = tid & 127;
    const bool isB = (tid >= 128);
    const int r0a = u >> 3, cca = u & 7;
    const int r0b = u >> 4, ccb = u & 15;

    auto prefetch = [&](int bufp, int k0) {
        if (!isB) {
#pragma unroll
            for (int p = 0; p < 8; p++) {
                int row = r0a + 16 * p;
                const __half* gp = Wt + (size_t)(o0 + row) * Cdim + k0 + cca * 8;
                __half* sp = Ab + ((size_t)bufp * 128 + row) * VKP + cca * 8;
                CP_ASYNC16(smem_cast(sp), gp);
            }
        } else {
#pragma unroll
            for (int p = 0; p < 8; p++) {
                int row = r0b + 8 * p;
                const __half* gp = Xb + (size_t)(k0 + row) * Ndim + n0 + ccb * 8;
                __half* sp = Bb + ((size_t)bufp * 64 + row) * SKP + ccb * 8;
                CP_ASYNC16(smem_cast(sp), gp);
            }
        }
        CP_COMMIT();
    };

    DECL_ACC;

    prefetch(0, 0);
    prefetch(1, 64);
    const int NIT = Cdim / 64;   // 4
    for (int it = 0; it < NIT; it++) {
        int buf = it & 1;
        if (it == NIT - 1) CP_WAIT0(); else CP_WAIT1();
        __syncthreads();
        const __half* At = Ab + (size_t)buf * 128 * VKP;
        const __half* Bt = Bb + (size_t)buf * 64 * SKP;
        F16_STEP_MKKN(At, Bt, wm, wn, j, r);
        __syncthreads();
        if (it + 2 < NIT) prefetch(buf, (it + 2) * 64);
    }

    const float scale = (sidx >= 0) ? s[sidx] : 1.f;
#pragma unroll
    for (int mi = 0; mi < 4; mi++)
#pragma unroll
        for (int r2 = 0; r2 < 2; r2++) {
            int m = o0 + wm + mi * 16 + g + r2 * 8;
            float bi = bias[m];
#pragma unroll
            for (int ni = 0; ni < 4; ni++) {
                int n = n0 + wn + ni * 8 + t * 2;
                size_t idx = (size_t)m * Ndim + n;
                float v0 = (acc[mi][ni][r2 * 2 + 0] + bi) * scale;
                float v1 = (acc[mi][ni][r2 * 2 + 1] + bi) * scale;
                *(__half2*)(dsth + idx) = __floats2half2_rn(v0, v1);
            }
        }
}

// =====================================================================
// ksum3 (fp16 in): KS[a] = fp16(float(Ka)+float(Kb))
// =====================================================================
__global__ void __launch_bounds__(256) ksum3_kernel(
    const __half* __restrict__ K0, const __half* __restrict__ K1,
    const __half* __restrict__ K2,
    __half* __restrict__ S0, __half* __restrict__ S1, __half* __restrict__ S2)
{
    size_t i = ((size_t)blockIdx.x * 256 + threadIdx.x) * 4;
#pragma unroll
    for (int h = 0; h < 2; h++) {
        float2 a = __half22float2(*(const __half2*)(K0 + i + h * 2));
        float2 b = __half22float2(*(const __half2*)(K1 + i + h * 2));
        float2 c = __half22float2(*(const __half2*)(K2 + i + h * 2));
        *(__half2*)(S0 + i + h * 2) = __floats2half2_rn(c.x + b.x, c.y + b.y);
        *(__half2*)(S1 + i + h * 2) = __floats2half2_rn(a.x + b.x, a.y + b.y);
        *(__half2*)(S2 + i + h * 2) = __floats2half2_rn(a.x + c.x, a.y + c.y);
    }
}

// =====================================================================
// scores fp16 (R12 form): S = (1/16) Q^T KS. grid (18, 18, 12)
// =====================================================================
#define SC_SMEM (2 * 2 * 64 * SKP * 2)   // 69632 B

__global__ void __launch_bounds__(256, 2) scores_h(Att3h A)
{
    extern __shared__ __half hsm[];
    __half* Ab = hsm;
    __half* Bb = hsm + 2 * 64 * SKP;

    const int z = blockIdx.z, a = z >> 2, b = z & 3;
    const int y0 = blockIdx.y * BM;
    const int z0 = blockIdx.x * BN;
    const int tid = threadIdx.x;
    const int warp = tid >> 5, lane = tid & 31;
    const int t = lane & 3;
    const int wm = (warp & 1) * 64, wn = (warp >> 1) * 32;
    const __half* Qb = A.Q[a]  + (size_t)b * CN;
    const __half* Kb = A.KS[a] + (size_t)b * CN;

    const int u  = tid & 127;
    const int r0 = u >> 4;
    const int cc = u & 15;
    const bool isB = (tid >= 128);
    const __half* gsrc = isB ? (Kb + z0) : (Qb + y0);
    __half* sbase = isB ? Bb : Ab;

    auto prefetch = [&](int bufp, int k0) {
#pragma unroll
        for (int p = 0; p < 8; p++) {
            int row = r0 + 8 * p;
            const __half* gp = gsrc + (size_t)(k0 + row) * Ndim + cc * 8;
            __half* sp = sbase + ((size_t)bufp * 64 + row) * SKP + cc * 8;
            CP_ASYNC16(smem_cast(sp), gp);
        }
        CP_COMMIT();
    };

    DECL_ACC;

    prefetch(0, 0);
    prefetch(1, 64);
    const int NIT = Cdim / 64;   // 4
    for (int it = 0; it < NIT; it++) {
        int buf = it & 1;
        if (it == NIT - 1) CP_WAIT0(); else CP_WAIT1();
        __syncthreads();
        const __half* At = Ab + (size_t)buf * 64 * SKP;
        const __half* Bt = Bb + (size_t)buf * 64 * SKP;
        const int j = lane >> 3, r = lane & 7;
#pragma unroll
        for (int ks = 0; ks < 64; ks += 16) {
            uint32_t af[4][4];
#pragma unroll
            for (int mi = 0; mi < 4; mi++) {
                int krow = ks + ((j & 2) ? 8 : 0) + r;
                int mo = wm + mi * 16 + ((j & 1) ? 8 : 0);
                ldsm4t(af[mi][0], af[mi][1], af[mi][2], af[mi][3],
                       smem_cast(At + (size_t)krow * SKP + mo));
            }
#pragma unroll
            for (int np = 0; np < 2; np++) {
                int krow = ks + ((j & 1) ? 8 : 0) + r;
                int no = wn + np * 16 + ((j & 2) ? 8 : 0);
                uint32_t b0, b1, b2, b3;
                ldsm4t(b0, b1, b2, b3, smem_cast(Bt + (size_t)krow * SKP + no));
                uint32_t bl[2] = { b0, b1 }, bh[2] = { b2, b3 };
#pragma unroll
                for (int mi = 0; mi < 4; mi++) {
                    mma_f16(acc[mi][np * 2 + 0], af[mi], bl);
                    mma_f16(acc[mi][np * 2 + 1], af[mi], bh);
                }
            }
        }
        __syncthreads();
        if (it + 2 < NIT) prefetch(buf, (it + 2) * 64);
    }

    __half* Sb = g_S3h + (size_t)z * NN;
    const int g = lane >> 2;
#pragma unroll
    for (int mi = 0; mi < 4; mi++)
#pragma unroll
        for (int r2 = 0; r2 < 2; r2++) {
            int y = y0 + wm + mi * 16 + g + r2 * 8;
#pragma unroll
            for (int ni = 0; ni < 4; ni++) {
                int zz = z0 + wn + ni * 8 + t * 2;
                size_t idx = (size_t)y * Ndim + zz;
                *(__half2*)(Sb + idx) = __floats2half2_rn(
                    acc[mi][ni][r2 * 2 + 0] * 0.0625f,
                    acc[mi][ni][r2 * 2 + 1] * 0.0625f);
            }
        }
}

// =====================================================================
// softmax: 2 rows per 256-thread block, half2 I/O
// =====================================================================
__global__ void __launch_bounds__(256) softmax_kernel()
{
    const int sub = threadIdx.x >> 7;
    const size_t row = (size_t)blockIdx.x * 2 + sub;
    __half2* p = (__half2*)(g_S3h + row * Ndim);
    const int t = threadIdx.x & 127;
    const int warp = threadIdx.x >> 5, lane = threadIdx.x & 31;
    __shared__ float redm[8], reds[8];

    float2 v[9];
#pragma unroll
    for (int i = 0; i < 9; i++) v[i] = __half22float2(p[t + i * 128]);

    float mx = fmaxf(v[0].x, v[0].y);
#pragma unroll
    for (int i = 1; i < 9; i++) mx = fmaxf(mx, fmaxf(v[i].x, v[i].y));
#pragma unroll
    for (int off = 16; off > 0; off >>= 1)
        mx = fmaxf(mx, __shfl_xor_sync(0xffffffffu, mx, off));
    if (lane == 0) redm[warp] = mx;
    __syncthreads();
    {
        int base = sub * 4;
        mx = fmaxf(fmaxf(redm[base], redm[base + 1]),
                   fmaxf(redm[base + 2], redm[base + 3]));
    }

    float sum = 0.f;
#pragma unroll
    for (int i = 0; i < 9; i++) {
        v[i].x = __expf(v[i].x - mx);
        v[i].y = __expf(v[i].y - mx);
        sum += v[i].x + v[i].y;
    }
#pragma unroll
    for (int off = 16; off > 0; off >>= 1)
        sum += __shfl_xor_sync(0xffffffffu, sum, off);
    if (lane == 0) reds[warp] = sum;
    __syncthreads();
    float inv;
    {
        int base = sub * 4;
        inv = 1.f / (reds[base] + reds[base + 1] + reds[base + 2] + reds[base + 3]);
    }
#pragma unroll
    for (int i = 0; i < 9; i++)
        p[t + i * 128] = __floats2half2_rn(v[i].x * inv, v[i].y * inv);
}

// =====================================================================
// AV fp16, block tile 256(c) x 64(n): each P row read by ONE block.
// 8 warps as 4(m) x 2(n); warp tile 64x32 (proven). grid (36, 1, 12)
// dst[c][n] = sum_m V[c][m] P[n][m]
// =====================================================================
#define AV_SMEM (2 * (256 + 64) * VKP * 2)   // 92160 B

__global__ void __launch_bounds__(256, 2) av_h(Att3h A)
{
    extern __shared__ __half hsm[];
    __half* Ab = hsm;                     // [2][256][VKP]
    __half* Bb = hsm + 2 * 256 * VKP;     // [2][64][VKP]

    const int z = blockIdx.z, a = z >> 2, b = z & 3;
    const int n0 = blockIdx.x * 64;
    const int tid = threadIdx.x;
    const int warp = tid >> 5, lane = tid & 31;
    const int t = lane & 3;
    const int j = lane >> 3, r = lane & 7;
    const int wm = (warp & 3) * 64, wn = (warp >> 2) * 32;
    const __half* Vb = A.V[a] + (size_t)b * CN;
    const __half* Pb = g_S3h + (size_t)z * NN;
    __half*      dst = A.O[a] + (size_t)b * CN;

    // loader: all 256 threads; A: 8 passes of 32 rows; B: 2 passes of 32 rows
    const int lrow = tid >> 3;    // 0..31
    const int lcc  = tid & 7;     // 16B chunk

    auto prefetch = [&](int bufp, int k0) {
#pragma unroll
        for (int p = 0; p < 8; p++) {
            int row = lrow + 32 * p;
            const __half* gp = Vb + (size_t)row * Ndim + k0 + lcc * 8;
            __half* sp = Ab + ((size_t)bufp * 256 + row) * VKP + lcc * 8;
            CP_ASYNC16(smem_cast(sp), gp);
        }
#pragma unroll
        for (int p = 0; p < 2; p++) {
            int row = lrow + 32 * p;
            const __half* gp = Pb + (size_t)(n0 + row) * Ndim + k0 + lcc * 8;
            __half* sp = Bb + ((size_t)bufp * 64 + row) * VKP + lcc * 8;
            CP_ASYNC16(smem_cast(sp), gp);
        }
        CP_COMMIT();
    };

    DECL_ACC;

    prefetch(0, 0);
    prefetch(1, 64);
    const int NIT = Ndim / 64;   // 36
    for (int it = 0; it < NIT; it++) {
        int buf = it & 1;
        if (it == NIT - 1) CP_WAIT0(); else CP_WAIT1();
        __syncthreads();
        const __half* At = Ab + (size_t)buf * 256 * VKP;
        const __half* Bt = Bb + (size_t)buf * 64 * VKP;
        F16_STEP_MKNK(At, Bt, wm, wn, j, r);
        __syncthreads();
        if (it + 2 < NIT) prefetch(buf, (it + 2) * 64);
    }

    const int g = lane >> 2;
#pragma unroll
    for (int mi = 0; mi < 4; mi++)
#pragma unroll
        for (int r2 = 0; r2 < 2; r2++) {
            int c = wm + mi * 16 + g + r2 * 8;
#pragma unroll
            for (int ni = 0; ni < 4; ni++) {
                int n = n0 + wn + ni * 8 + t * 2;
                *(__half2*)(dst + (size_t)c * Ndim + n) = __floats2half2_rn(
                    acc[mi][ni][r2 * 2 + 0], acc[mi][ni][r2 * 2 + 1]);
            }
        }
}

// =====================================================================
// gate fp16 (R12 form): F = sigmoid(Wg X + bg) * X, F fp16. grid (18,2,12)
// =====================================================================
__global__ void __launch_bounds__(256, 2) gate_h3(
    const __half* __restrict__ WgH, const float* __restrict__ bg)
{
    extern __shared__ __half hsm[];
    __half* Ab = hsm;                     // [2][128][VKP]
    __half* Bb = hsm + 2 * 128 * VKP;     // [2][64][SKP]

    const int z = blockIdx.z, a = z >> 2, b = z & 3;
    const int o0 = blockIdx.y * BM;
    const int n0 = blockIdx.x * BN;
    const int tid = threadIdx.x;
    const int warp = tid >> 5, lane = tid & 31;
    const int g = lane >> 2, t = lane & 3;
    const int jj = lane >> 3, rr = lane & 7;
    const int wm = (warp & 1) * 64, wn = (warp >> 1) * 32;
    const __half* Xb = g_Wh[a] + (size_t)b * CN;
    __half*      F  = g_F3h[a] + (size_t)b * CN;

    const int u = tid & 127;
    const bool isB = (tid >= 128);
    const int r0a = u >> 3, cca = u & 7;
    const int r0b = u >> 4, ccb = u & 15;

    auto prefetch = [&](int bufp, int k0) {
        if (!isB) {
#pragma unroll
            for (int p = 0; p < 8; p++) {
                int row = r0a + 16 * p;
                const __half* gp = WgH + (size_t)(o0 + row) * Cdim + k0 + cca * 8;
                __half* sp = Ab + ((size_t)bufp * 128 + row) * VKP + cca * 8;
                CP_ASYNC16(smem_cast(sp), gp);
            }
        } else {
#pragma unroll
            for (int p = 0; p < 8; p++) {
                int row = r0b + 8 * p;
                const __half* gp = Xb + (size_t)(k0 + row) * Ndim + n0 + ccb * 8;
                __half* sp = Bb + ((size_t)bufp * 64 + row) * SKP + ccb * 8;
                CP_ASYNC16(smem_cast(sp), gp);
            }
        }
        CP_COMMIT();
    };

    DECL_ACC;

    prefetch(0, 0);
    prefetch(1, 64);
    const int NIT = Cdim / 64;   // 4
    for (int it = 0; it < NIT; it++) {
        int buf = it & 1;
        if (it == NIT - 1) CP_WAIT0(); else CP_WAIT1();
        __syncthreads();
        const __half* At = Ab + (size_t)buf * 128 * VKP;
        const __half* Bt = Bb + (size_t)buf * 64 * SKP;
        F16_STEP_MKKN(At, Bt, wm, wn, jj, rr);
        __syncthreads();
        if (it + 2 < NIT) prefetch(buf, (it + 2) * 64);
    }

#pragma unroll
    for (int mi = 0; mi < 4; mi++)
#pragma unroll
        for (int r2 = 0; r2 < 2; r2++) {
            int o = o0 + wm + mi * 16 + g + r2 * 8;
            float bi = bg[o];
#pragma unroll
            for (int ni = 0; ni < 4; ni++) {
                int n = n0 + wn + ni * 8 + t * 2;
                size_t idx = (size_t)o * Ndim + n;
                __half2 xh = *(const __half2*)(Xb + idx);
                float x0 = __low2float(xh), x1 = __high2float(xh);
                float g0 = acc[mi][ni][r2 * 2 + 0] + bi;
                float g1 = acc[mi][ni][r2 * 2 + 1] + bi;
                *(__half2*)(F + idx) = __floats2half2_rn(
                    x0 / (1.f + __expf(-g0)),
                    x1 / (1.f + __expf(-g1)));
            }
        }
}

// =====================================================================
// final fp16 (R12 form): out = WoH @ (F0+F1+F2) + bo. grid (18, 2, 4)
// =====================================================================
__global__ void __launch_bounds__(256, 2) final_h(
    const __half* __restrict__ WoH, const float* __restrict__ bo,
    float* __restrict__ out)
{
    extern __shared__ __half hsm[];
    __half* Ab = hsm;                     // [2][128][VKP]
    __half* Bb = hsm + 2 * 128 * VKP;     // [2][64][SKP]

    const int b  = blockIdx.z;
    const int o0 = blockIdx.y * BM;
    const int n0 = blockIdx.x * BN;
    const int tid = threadIdx.x;
    const int warp = tid >> 5, lane = tid & 31;
    const int g = lane >> 2, t = lane & 3;
    const int jj = lane >> 3, rr = lane & 7;
    const int wm = (warp & 1) * 64, wn = (warp >> 1) * 32;
    const __half* F0 = g_F3h[0] + (size_t)b * CN;
    const __half* F1 = g_F3h[1] + (size_t)b * CN;
    const __half* F2 = g_F3h[2] + (size_t)b * CN;
    float* dst = out + (size_t)b * CN;

    const int u = tid & 127;
    const bool isB = (tid >= 128);
    const int r0a = u >> 3, cca = u & 7;
    const int r0b = u >> 4, ccb = u & 15;

    auto prefetchA = [&](int bufp, int k0) {
        if (!isB) {
#pragma unroll
            for (int p = 0; p < 8; p++) {
                int row = r0a + 16 * p;
                const __half* gp = WoH + (size_t)(o0 + row) * Cdim + k0 + cca * 8;
                __half* sp = Ab + ((size_t)bufp * 128 + row) * VKP + cca * 8;
                CP_ASYNC16(smem_cast(sp), gp);
            }
        }
        CP_COMMIT();
    };

    __half2 breg[8][4];
    auto loadB = [&](int k0) {
        if (isB) {
#pragma unroll
            for (int p = 0; p < 8; p++) {
                int row = r0b + 8 * p;
                size_t off = (size_t)(k0 + row) * Ndim + n0 + ccb * 8;
#pragma unroll
                for (int c = 0; c < 4; c++) {
                    float2 a0 = __half22float2(*(const __half2*)(F0 + off + c * 2));
                    float2 a1 = __half22float2(*(const __half2*)(F1 + off + c * 2));
                    float2 a2 = __half22float2(*(const __half2*)(F2 + off + c * 2));
                    breg[p][c] = __floats2half2_rn(a0.x + a1.x + a2.x,
                                                   a0.y + a1.y + a2.y);
                }
            }
        }
    };
    auto storeB = [&](int bufp) {
        if (isB) {
#pragma unroll
            for (int p = 0; p < 8; p++) {
                int row = r0b + 8 * p;
                __half2* sp = (__half2*)(Bb + ((size_t)bufp * 64 + row) * SKP + ccb * 8);
#pragma unroll
                for (int c = 0; c < 4; c++) sp[c] = breg[p][c];
            }
        }
    };

    DECL_ACC;

    prefetchA(0, 0);
    prefetchA(1, 64);
    loadB(0); storeB(0);
    loadB(64);
    const int NIT = Cdim / 64;   // 4
    for (int it = 0; it < NIT; it++) {
        int buf = it & 1;
        if (it == NIT - 1) CP_WAIT0(); else CP_WAIT1();
        __syncthreads();
        const __half* At = Ab + (size_t)buf * 128 * VKP;
        const __half* Bt = Bb + (size_t)buf * 64 * SKP;
        F16_STEP_MKKN(At, Bt, wm, wn, jj, rr);
        __syncthreads();
        if (it + 2 < NIT) prefetchA(buf, (it + 2) * 64);
        if (it + 1 < NIT) storeB(buf ^ 1);
        if (it + 2 < NIT) loadB((it + 2) * 64);
    }

#pragma unroll
    for (int mi = 0; mi < 4; mi++)
#pragma unroll
        for (int r2 = 0; r2 < 2; r2++) {
            int o = o0 + wm + mi * 16 + g + r2 * 8;
            float bi = bo[o];
#pragma unroll
            for (int ni = 0; ni < 4; ni++) {
                int n = n0 + wn + ni * 8 + t * 2;
                size_t idx = (size_t)o * Ndim + n;
                float2 v = { acc[mi][ni][r2 * 2 + 0] + bi,
                             acc[mi][ni][r2 * 2 + 1] + bi };
                *(float2*)(dst + idx) = v;
            }
        }
}

// =====================================================================
// launch
// =====================================================================
extern "C" void kernel_launch(void* const* d_in, const int* in_sizes, int n_in,
                              void* d_out, int out_size)
{
    const float* x[3] = { (const float*)d_in[0], (const float*)d_in[1], (const float*)d_in[2] };
    const float* s = (const float*)d_in[3];
    const float *wq[3], *bq[3], *wk[3], *bk[3], *wv[3], *bv[3];
    for (int m = 0; m < 3; m++) {
        wq[m] = (const float*)d_in[4 + 6 * m];
        bq[m] = (const float*)d_in[5 + 6 * m];
        wk[m] = (const float*)d_in[6 + 6 * m];
        bk[m] = (const float*)d_in[7 + 6 * m];
        wv[m] = (const float*)d_in[8 + 6 * m];
        bv[m] = (const float*)d_in[9 + 6 * m];
    }
    const float* wg = (const float*)d_in[22];
    const float* bg = (const float*)d_in[23];
    const float* wo = (const float*)d_in[24];
    const float* bo = (const float*)d_in[25];
    float* out = (float*)d_out;

    __half *gH, *gXh, *gWT, *gWh, *gKh;
    cudaGetSymbolAddress((void**)&gH,  g_H);
    cudaGetSymbolAddress((void**)&gXh, g_Xh);
    cudaGetSymbolAddress((void**)&gWT, g_WT);
    cudaGetSymbolAddress((void**)&gWh, g_Wh);
    cudaGetSymbolAddress((void**)&gKh, g_Kh);

    __half *Kh[3], *Qh[3], *KSh[3], *Vh[3], *Xh[3], *Wout[3];
    for (int m = 0; m < 3; m++) {
        Kh[m]  = gKh + (size_t)m * PLANE;
        Qh[m]  = gH + (size_t)(0 + m) * PLANE;
        KSh[m] = gH + (size_t)(3 + m) * PLANE;
        Vh[m]  = gH + (size_t)(6 + m) * PLANE;
        Xh[m]  = gXh + (size_t)m * PLANE;
        Wout[m] = gWh + (size_t)m * PLANE;
    }
    __half* WqH[3]; __half* WkH[3]; __half* WvH[3];
    for (int m = 0; m < 3; m++) {
        WqH[m] = gWT + (size_t)(3 * m + 0) * Cdim * Cdim;
        WkH[m] = gWT + (size_t)(3 * m + 1) * Cdim * Cdim;
        WvH[m] = gWT + (size_t)(3 * m + 2) * Cdim * Cdim;
    }
    __half* WgH = gWT + (size_t)9 * Cdim * Cdim;
    __half* WoH = gWT + (size_t)10 * Cdim * Cdim;

    W11 WC;
    for (int m = 0; m < 3; m++) {
        WC.src[3 * m + 0] = wq[m];
        WC.src[3 * m + 1] = wk[m];
        WC.src[3 * m + 2] = wv[m];
    }
    WC.src[9]  = wg;
    WC.src[10] = wo;

    Proj9 P;
    for (int m = 0; m < 3; m++) {
        P.X[3 * m + 0] = Xh[m]; P.W[3 * m + 0] = WqH[m]; P.B[3 * m + 0] = bq[m];
        P.DH[3 * m + 0] = Qh[m]; P.sidx[3 * m + 0] = m;
        P.X[3 * m + 1] = Xh[m]; P.W[3 * m + 1] = WkH[m]; P.B[3 * m + 1] = bk[m];
        P.DH[3 * m + 1] = Kh[m]; P.sidx[3 * m + 1] = m;
        P.X[3 * m + 2] = Xh[m]; P.W[3 * m + 2] = WvH[m]; P.B[3 * m + 2] = bv[m];
        P.DH[3 * m + 2] = Vh[m]; P.sidx[3 * m + 2] = -1;
    }

    // attends: w_rgb(Q0; K2+K1; V0), w_depth(Q2; K0+K1; V2), w_thermal(Q1; K0+K2; V1)
    Att3h A;
    const int qi[3] = { 0, 2, 1 };
    for (int a = 0; a < 3; a++) {
        A.Q[a]  = Qh[qi[a]];
        A.KS[a] = KSh[a];
        A.V[a]  = Vh[qi[a]];
        A.O[a]  = Wout[a];
    }

    cudaFuncSetAttribute(proj_h9,  cudaFuncAttributeMaxDynamicSharedMemorySize, PJ_SMEM);
    cudaFuncSetAttribute(scores_h, cudaFuncAttributeMaxDynamicSharedMemorySize, SC_SMEM);
    cudaFuncSetAttribute(av_h,     cudaFuncAttributeMaxDynamicSharedMemorySize, AV_SMEM);
    cudaFuncSetAttribute(gate_h3,  cudaFuncAttributeMaxDynamicSharedMemorySize, PJ_SMEM);
    cudaFuncSetAttribute(final_h,  cudaFuncAttributeMaxDynamicSharedMemorySize, PJ_SMEM);

    dim3 blk(256);
    cvt_x3 <<<dim3(PLANE / 1024, 3), blk>>>(x[0], x[1], x[2], Xh[0], Xh[1], Xh[2]);
    cvt_w11<<<dim3(Cdim * Cdim / 1024, 11), blk>>>(WC, gWT);
    proj_h9<<<dim3(Ndim / BN, Cdim / BM, 36), blk, PJ_SMEM>>>(P, s);
    ksum3_kernel<<<dim3(PLANE / 1024), blk>>>(Kh[0], Kh[1], Kh[2], KSh[0], KSh[1], KSh[2]);
    scores_h<<<dim3(Ndim / BN, Ndim / BM, 12), blk, SC_SMEM>>>(A);
    softmax_kernel<<<dim3(3 * Bdim * Ndim / 2), blk>>>();
    av_h   <<<dim3(Ndim / 64, 1, 12), blk, AV_SMEM>>>(A);
    gate_h3<<<dim3(Ndim / BN, Cdim / BM, 12), blk, PJ_SMEM>>>(WgH, bg);
    final_h<<<dim3(Ndim / BN, Cdim / BM, 4), blk, PJ_SMEM>>>(WoH, bo, out);
}

// round 15
// speedup vs baseline: 1.0813x; 1.0393x over previous
#include <cuda_runtime.h>
#include <cuda_fp16.h>
#include <cstdint>
#include <math.h>

#define Bdim 4
#define Cdim 256
#define Ndim 2304      // 48*48
#define PLANE (Bdim*Cdim*Ndim)
#define CN   (Cdim*Ndim)
#define NN   ((size_t)Ndim*Ndim)

#define BM 128
#define BN 128
#define SKP 136        // fp16 [k][*] stride (272B)
#define VKP 72         // fp16 [row][k] stride (144B)

// ---- scratch ----
__device__ __half g_Xh[3][PLANE];                    // fp16 inputs
__device__ __half g_WT[11][Cdim * Cdim];             // fp16 weights
__device__ __half g_Kh[3][PLANE];                    // raw fp16 K
__device__ __half g_H[9][PLANE];                     // Q0..2, KS0..2, V0..2
__device__ __half g_S3h[(size_t)3 * Bdim * NN];      // scores / probs
__device__ __half g_F3h[3][PLANE];                   // gated outputs

// ---- fp16 mma + ldmatrix ----
__device__ __forceinline__ void mma_f16(float c[4], const uint32_t a[4], const uint32_t b[2]) {
    asm volatile(
        "mma.sync.aligned.m16n8k16.row.col.f32.f16.f16.f32 "
        "{%0,%1,%2,%3}, {%4,%5,%6,%7}, {%8,%9}, {%0,%1,%2,%3};"
        : "+f"(c[0]), "+f"(c[1]), "+f"(c[2]), "+f"(c[3])
        : "r"(a[0]), "r"(a[1]), "r"(a[2]), "r"(a[3]), "r"(b[0]), "r"(b[1]));
}
__device__ __forceinline__ void ldsm4(uint32_t& r0, uint32_t& r1, uint32_t& r2, uint32_t& r3, uint32_t a) {
    asm volatile("ldmatrix.sync.aligned.m8n8.x4.shared.b16 {%0,%1,%2,%3}, [%4];"
        : "=r"(r0), "=r"(r1), "=r"(r2), "=r"(r3) : "r"(a));
}
__device__ __forceinline__ void ldsm4t(uint32_t& r0, uint32_t& r1, uint32_t& r2, uint32_t& r3, uint32_t a) {
    asm volatile("ldmatrix.sync.aligned.m8n8.x4.trans.shared.b16 {%0,%1,%2,%3}, [%4];"
        : "=r"(r0), "=r"(r1), "=r"(r2), "=r"(r3) : "r"(a));
}

// ---- cp.async ----
__device__ __forceinline__ uint32_t smem_cast(const void* p) {
    return (uint32_t)__cvta_generic_to_shared(p);
}
#define CP_ASYNC16(dst_u32, gptr) \
    asm volatile("cp.async.cg.shared.global [%0], [%1], 16;" :: "r"(dst_u32), "l"(gptr))
#define CP_COMMIT() asm volatile("cp.async.commit_group;" ::: "memory")
#define CP_WAIT1()  asm volatile("cp.async.wait_group 1;" ::: "memory")
#define CP_WAIT0()  asm volatile("cp.async.wait_group 0;" ::: "memory")

#define DECL_ACC float acc[4][4][4]; \
    _Pragma("unroll") for (int mi = 0; mi < 4; mi++) \
    _Pragma("unroll") for (int ni = 0; ni < 4; ni++) \
    _Pragma("unroll") for (int r = 0; r < 4; r++) acc[mi][ni][r] = 0.f;

#define REINIT_ACC \
    _Pragma("unroll") for (int mi = 0; mi < 4; mi++) \
    _Pragma("unroll") for (int ni = 0; ni < 4; ni++) \
    _Pragma("unroll") for (int r = 0; r < 4; r++) acc[mi][ni][r] = 0.f;

// fp16 GEMM step: A [m][k] VKP (ldsm), B [k][n] stride BSTR (ldsm.trans); 64x32 warp tile
#define F16_STEP_MKKN(At, Bt, BSTR, wm, wn, j, r) \
    _Pragma("unroll") \
    for (int ks = 0; ks < 64; ks += 16) { \
        uint32_t af[4][4]; \
        _Pragma("unroll") \
        for (int mi = 0; mi < 4; mi++) { \
            int mrow = (wm) + mi * 16 + (((j) & 1) ? 8 : 0) + (r); \
            int ko = ks + (((j) & 2) ? 8 : 0); \
            ldsm4(af[mi][0], af[mi][1], af[mi][2], af[mi][3], \
                  smem_cast((At) + (size_t)mrow * VKP + ko)); \
        } \
        _Pragma("unroll") \
        for (int np = 0; np < 2; np++) { \
            int krow = ks + (((j) & 1) ? 8 : 0) + (r); \
            int no = (wn) + np * 16 + (((j) & 2) ? 8 : 0); \
            uint32_t b0, b1, b2, b3; \
            ldsm4t(b0, b1, b2, b3, smem_cast((Bt) + (size_t)krow * (BSTR) + no)); \
            uint32_t bl[2] = { b0, b1 }, bh[2] = { b2, b3 }; \
            _Pragma("unroll") \
            for (int mi = 0; mi < 4; mi++) { \
                mma_f16(acc[mi][np * 2 + 0], af[mi], bl); \
                mma_f16(acc[mi][np * 2 + 1], af[mi], bh); \
            } \
        } \
    }

// fp16 GEMM step: A [m][k] VKP, B [n][k] VKP (both ldsm); 64x32 warp tile
#define F16_STEP_MKNK(At, Bt, wm, wn, j, r) \
    _Pragma("unroll") \
    for (int ks = 0; ks < 64; ks += 16) { \
        uint32_t af[4][4]; \
        _Pragma("unroll") \
        for (int mi = 0; mi < 4; mi++) { \
            int mrow = (wm) + mi * 16 + (((j) & 1) ? 8 : 0) + (r); \
            int ko = ks + (((j) & 2) ? 8 : 0); \
            ldsm4(af[mi][0], af[mi][1], af[mi][2], af[mi][3], \
                  smem_cast((At) + (size_t)mrow * VKP + ko)); \
        } \
        _Pragma("unroll") \
        for (int np = 0; np < 2; np++) { \
            int nrow = (wn) + np * 16 + (((j) & 2) ? 8 : 0) + (r); \
            int ko = ks + (((j) & 1) ? 8 : 0); \
            uint32_t b0, b1, b2, b3; \
            ldsm4(b0, b1, b2, b3, smem_cast((Bt) + (size_t)nrow * VKP + ko)); \
            uint32_t bl[2] = { b0, b1 }, bh[2] = { b2, b3 }; \
            _Pragma("unroll") \
            for (int mi = 0; mi < 4; mi++) { \
                mma_f16(acc[mi][np * 2 + 0], af[mi], bl); \
                mma_f16(acc[mi][np * 2 + 1], af[mi], bh); \
            } \
        } \
    }

// ---- arg structs ----
struct Proj9 {
    const __half* X[9]; const __half* W[9]; const float* B[9];
    __half* DH[9]; int sidx[9];
};
struct Att3h {
    const __half* Q[3]; const __half* KS[3]; const __half* V[3];
};

// =====================================================================
// cvt kernels
// =====================================================================
__global__ void __launch_bounds__(256) cvt_x3(
    const float* __restrict__ x0, const float* __restrict__ x1,
    const float* __restrict__ x2,
    __half* __restrict__ d0, __half* __restrict__ d1, __half* __restrict__ d2)
{
    const float* src = (blockIdx.y == 0) ? x0 : (blockIdx.y == 1) ? x1 : x2;
    __half* dst      = (blockIdx.y == 0) ? d0 : (blockIdx.y == 1) ? d1 : d2;
    size_t i = ((size_t)blockIdx.x * 256 + threadIdx.x) * 4;
    float4 v = *(const float4*)(src + i);
    *(__half2*)(dst + i)     = __floats2half2_rn(v.x, v.y);
    *(__half2*)(dst + i + 2) = __floats2half2_rn(v.z, v.w);
}

struct W11 { const float* src[11]; };
__global__ void __launch_bounds__(256) cvt_w11(W11 W, __half* __restrict__ base)
{
    const float* src = W.src[blockIdx.y];
    __half* dst = base + (size_t)blockIdx.y * Cdim * Cdim;
    size_t i = ((size_t)blockIdx.x * 256 + threadIdx.x) * 4;
    float4 v = *(const float4*)(src + i);
    *(__half2*)(dst + i)     = __floats2half2_rn(v.x, v.y);
    *(__half2*)(dst + i + 2) = __floats2half2_rn(v.z, v.w);
}

// =====================================================================
// proj fp16 (R12 form): grid (18, 2, 36)
// =====================================================================
#define PJ_SMEM (2*128*VKP*2 + 2*64*SKP*2)   // 71680 B

__global__ void __launch_bounds__(256, 2) proj_h9(Proj9 P, const float* __restrict__ s)
{
    extern __shared__ __half hsm[];
    __half* Ab = hsm;                     // [2][128][VKP]
    __half* Bb = hsm + 2 * 128 * VKP;     // [2][64][SKP]

    const int z = blockIdx.z, job = z >> 2, b = z & 3;
    const int o0 = blockIdx.y * BM;
    const int n0 = blockIdx.x * BN;
    const int tid = threadIdx.x;
    const int warp = tid >> 5, lane = tid & 31;
    const int g = lane >> 2, t = lane & 3;
    const int j = lane >> 3, r = lane & 7;
    const int wm = (warp & 1) * 64, wn = (warp >> 1) * 32;

    const __half* Xb   = P.X[job] + (size_t)b * CN;
    const __half* Wt   = P.W[job];
    const float*  bias = P.B[job];
    __half* dsth = P.DH[job] + (size_t)b * CN;
    const int sidx = P.sidx[job];

    const int u = tid & 127;
    const bool isB = (tid >= 128);
    const int r0a = u >> 3, cca = u & 7;
    const int r0b = u >> 4, ccb = u & 15;

    auto prefetch = [&](int bufp, int k0) {
        if (!isB) {
#pragma unroll
            for (int p = 0; p < 8; p++) {
                int row = r0a + 16 * p;
                const __half* gp = Wt + (size_t)(o0 + row) * Cdim + k0 + cca * 8;
                __half* sp = Ab + ((size_t)bufp * 128 + row) * VKP + cca * 8;
                CP_ASYNC16(smem_cast(sp), gp);
            }
        } else {
#pragma unroll
            for (int p = 0; p < 8; p++) {
                int row = r0b + 8 * p;
                const __half* gp = Xb + (size_t)(k0 + row) * Ndim + n0 + ccb * 8;
                __half* sp = Bb + ((size_t)bufp * 64 + row) * SKP + ccb * 8;
                CP_ASYNC16(smem_cast(sp), gp);
            }
        }
        CP_COMMIT();
    };

    DECL_ACC;

    prefetch(0, 0);
    prefetch(1, 64);
    const int NIT = Cdim / 64;   // 4
    for (int it = 0; it < NIT; it++) {
        int buf = it & 1;
        if (it == NIT - 1) CP_WAIT0(); else CP_WAIT1();
        __syncthreads();
        const __half* At = Ab + (size_t)buf * 128 * VKP;
        const __half* Bt = Bb + (size_t)buf * 64 * SKP;
        F16_STEP_MKKN(At, Bt, SKP, wm, wn, j, r);
        __syncthreads();
        if (it + 2 < NIT) prefetch(buf, (it + 2) * 64);
    }

    const float scale = (sidx >= 0) ? s[sidx] : 1.f;
#pragma unroll
    for (int mi = 0; mi < 4; mi++)
#pragma unroll
        for (int r2 = 0; r2 < 2; r2++) {
            int m = o0 + wm + mi * 16 + g + r2 * 8;
            float bi = bias[m];
#pragma unroll
            for (int ni = 0; ni < 4; ni++) {
                int n = n0 + wn + ni * 8 + t * 2;
                size_t idx = (size_t)m * Ndim + n;
                float v0 = (acc[mi][ni][r2 * 2 + 0] + bi) * scale;
                float v1 = (acc[mi][ni][r2 * 2 + 1] + bi) * scale;
                *(__half2*)(dsth + idx) = __floats2half2_rn(v0, v1);
            }
        }
}

// =====================================================================
// ksum3 (fp16 in)
// =====================================================================
__global__ void __launch_bounds__(256) ksum3_kernel(
    const __half* __restrict__ K0, const __half* __restrict__ K1,
    const __half* __restrict__ K2,
    __half* __restrict__ S0, __half* __restrict__ S1, __half* __restrict__ S2)
{
    size_t i = ((size_t)blockIdx.x * 256 + threadIdx.x) * 4;
#pragma unroll
    for (int h = 0; h < 2; h++) {
        float2 a = __half22float2(*(const __half2*)(K0 + i + h * 2));
        float2 b = __half22float2(*(const __half2*)(K1 + i + h * 2));
        float2 c = __half22float2(*(const __half2*)(K2 + i + h * 2));
        *(__half2*)(S0 + i + h * 2) = __floats2half2_rn(c.x + b.x, c.y + b.y);
        *(__half2*)(S1 + i + h * 2) = __floats2half2_rn(a.x + b.x, a.y + b.y);
        *(__half2*)(S2 + i + h * 2) = __floats2half2_rn(a.x + c.x, a.y + c.y);
    }
}

// =====================================================================
// scores fp16 (R12 form): S = (1/16) Q^T KS. grid (18, 18, 12)
// =====================================================================
#define SC_SMEM (2 * 2 * 64 * SKP * 2)   // 69632 B

__global__ void __launch_bounds__(256, 2) scores_h(Att3h A)
{
    extern __shared__ __half hsm[];
    __half* Ab = hsm;
    __half* Bb = hsm + 2 * 64 * SKP;

    const int z = blockIdx.z, a = z >> 2, b = z & 3;
    const int y0 = blockIdx.y * BM;
    const int z0 = blockIdx.x * BN;
    const int tid = threadIdx.x;
    const int warp = tid >> 5, lane = tid & 31;
    const int t = lane & 3;
    const int wm = (warp & 1) * 64, wn = (warp >> 1) * 32;
    const __half* Qb = A.Q[a]  + (size_t)b * CN;
    const __half* Kb = A.KS[a] + (size_t)b * CN;

    const int u  = tid & 127;
    const int r0 = u >> 4;
    const int cc = u & 15;
    const bool isB = (tid >= 128);
    const __half* gsrc = isB ? (Kb + z0) : (Qb + y0);
    __half* sbase = isB ? Bb : Ab;

    auto prefetch = [&](int bufp, int k0) {
#pragma unroll
        for (int p = 0; p < 8; p++) {
            int row = r0 + 8 * p;
            const __half* gp = gsrc + (size_t)(k0 + row) * Ndim + cc * 8;
            __half* sp = sbase + ((size_t)bufp * 64 + row) * SKP + cc * 8;
            CP_ASYNC16(smem_cast(sp), gp);
        }
        CP_COMMIT();
    };

    DECL_ACC;

    prefetch(0, 0);
    prefetch(1, 64);
    const int NIT = Cdim / 64;   // 4
    for (int it = 0; it < NIT; it++) {
        int buf = it & 1;
        if (it == NIT - 1) CP_WAIT0(); else CP_WAIT1();
        __syncthreads();
        const __half* At = Ab + (size_t)buf * 64 * SKP;
        const __half* Bt = Bb + (size_t)buf * 64 * SKP;
        const int j = lane >> 3, r = lane & 7;
#pragma unroll
        for (int ks = 0; ks < 64; ks += 16) {
            uint32_t af[4][4];
#pragma unroll
            for (int mi = 0; mi < 4; mi++) {
                int krow = ks + ((j & 2) ? 8 : 0) + r;
                int mo = wm + mi * 16 + ((j & 1) ? 8 : 0);
                ldsm4t(af[mi][0], af[mi][1], af[mi][2], af[mi][3],
                       smem_cast(At + (size_t)krow * SKP + mo));
            }
#pragma unroll
            for (int np = 0; np < 2; np++) {
                int krow = ks + ((j & 1) ? 8 : 0) + r;
                int no = wn + np * 16 + ((j & 2) ? 8 : 0);
                uint32_t b0, b1, b2, b3;
                ldsm4t(b0, b1, b2, b3, smem_cast(Bt + (size_t)krow * SKP + no));
                uint32_t bl[2] = { b0, b1 }, bh[2] = { b2, b3 };
#pragma unroll
                for (int mi = 0; mi < 4; mi++) {
                    mma_f16(acc[mi][np * 2 + 0], af[mi], bl);
                    mma_f16(acc[mi][np * 2 + 1], af[mi], bh);
                }
            }
        }
        __syncthreads();
        if (it + 2 < NIT) prefetch(buf, (it + 2) * 64);
    }

    __half* Sb = g_S3h + (size_t)z * NN;
    const int g = lane >> 2;
#pragma unroll
    for (int mi = 0; mi < 4; mi++)
#pragma unroll
        for (int r2 = 0; r2 < 2; r2++) {
            int y = y0 + wm + mi * 16 + g + r2 * 8;
#pragma unroll
            for (int ni = 0; ni < 4; ni++) {
                int zz = z0 + wn + ni * 8 + t * 2;
                size_t idx = (size_t)y * Ndim + zz;
                *(__half2*)(Sb + idx) = __floats2half2_rn(
                    acc[mi][ni][r2 * 2 + 0] * 0.0625f,
                    acc[mi][ni][r2 * 2 + 1] * 0.0625f);
            }
        }
}

// =====================================================================
// softmax: 2 rows per 256-thread block, half2 I/O
// =====================================================================
__global__ void __launch_bounds__(256) softmax_kernel()
{
    const int sub = threadIdx.x >> 7;
    const size_t row = (size_t)blockIdx.x * 2 + sub;
    __half2* p = (__half2*)(g_S3h + row * Ndim);
    const int t = threadIdx.x & 127;
    const int warp = threadIdx.x >> 5, lane = threadIdx.x & 31;
    __shared__ float redm[8], reds[8];

    float2 v[9];
#pragma unroll
    for (int i = 0; i < 9; i++) v[i] = __half22float2(p[t + i * 128]);

    float mx = fmaxf(v[0].x, v[0].y);
#pragma unroll
    for (int i = 1; i < 9; i++) mx = fmaxf(mx, fmaxf(v[i].x, v[i].y));
#pragma unroll
    for (int off = 16; off > 0; off >>= 1)
        mx = fmaxf(mx, __shfl_xor_sync(0xffffffffu, mx, off));
    if (lane == 0) redm[warp] = mx;
    __syncthreads();
    {
        int base = sub * 4;
        mx = fmaxf(fmaxf(redm[base], redm[base + 1]),
                   fmaxf(redm[base + 2], redm[base + 3]));
    }

    float sum = 0.f;
#pragma unroll
    for (int i = 0; i < 9; i++) {
        v[i].x = __expf(v[i].x - mx);
        v[i].y = __expf(v[i].y - mx);
        sum += v[i].x + v[i].y;
    }
#pragma unroll
    for (int off = 16; off > 0; off >>= 1)
        sum += __shfl_xor_sync(0xffffffffu, sum, off);
    if (lane == 0) reds[warp] = sum;
    __syncthreads();
    float inv;
    {
        int base = sub * 4;
        inv = 1.f / (reds[base] + reds[base + 1] + reds[base + 2] + reds[base + 3]);
    }
#pragma unroll
    for (int i = 0; i < 9; i++)
        p[t + i * 128] = __floats2half2_rn(v[i].x * inv, v[i].y * inv);
}

// =====================================================================
// FUSED av+gate, block tile 256(c) x 64(n). grid (36, 1, 12)
// phase 1: slab[c][n] = sum_m V[c][m] P[n][m]  (into smem)
// phase 2: F[o][n] = sigmoid(sum_c Wg[o][c] slab[c][n] + bg[o]) * slab[o][n]
// 8 warps as 4(m) x 2(n), warp tile 64x32
// =====================================================================
#define AV_SMEM (2 * (256 + 64) * VKP * 2)   // 92160 B
// phase-2 overlay: slab [256][VKP] at 0; Wg tile [256][VKP] at 256*VKP

__global__ void __launch_bounds__(256, 2) avgate_h(
    Att3h A, const __half* __restrict__ WgH, const float* __restrict__ bg)
{
    extern __shared__ __half hsm[];
    __half* Ab = hsm;                     // ph1: [2][256][VKP]
    __half* Bb = hsm + 2 * 256 * VKP;     // ph1: [2][64][VKP]
    __half* Sl = hsm;                     // ph2: [256][VKP]
    __half* Wa = hsm + 256 * VKP;         // ph2: [256][VKP]

    const int z = blockIdx.z, a = z >> 2, b = z & 3;
    const int n0 = blockIdx.x * 64;
    const int tid = threadIdx.x;
    const int warp = tid >> 5, lane = tid & 31;
    const int t = lane & 3;
    const int j = lane >> 3, r = lane & 7;
    const int wm = (warp & 3) * 64, wn = (warp >> 2) * 32;
    const __half* Vb = A.V[a] + (size_t)b * CN;
    const __half* Pb = g_S3h + (size_t)z * NN;
    __half*       F  = g_F3h[a] + (size_t)b * CN;

    const int lrow = tid >> 3;    // 0..31
    const int lcc  = tid & 7;

    auto prefetch = [&](int bufp, int k0) {
#pragma unroll
        for (int p = 0; p < 8; p++) {
            int row = lrow + 32 * p;
            const __half* gp = Vb + (size_t)row * Ndim + k0 + lcc * 8;
            __half* sp = Ab + ((size_t)bufp * 256 + row) * VKP + lcc * 8;
            CP_ASYNC16(smem_cast(sp), gp);
        }
#pragma unroll
        for (int p = 0; p < 2; p++) {
            int row = lrow + 32 * p;
            const __half* gp = Pb + (size_t)(n0 + row) * Ndim + k0 + lcc * 8;
            __half* sp = Bb + ((size_t)bufp * 64 + row) * VKP + lcc * 8;
            CP_ASYNC16(smem_cast(sp), gp);
        }
        CP_COMMIT();
    };

    DECL_ACC;

    // ---- phase 1: AV ----
    prefetch(0, 0);
    prefetch(1, 64);
    const int NIT = Ndim / 64;   // 36
    for (int it = 0; it < NIT; it++) {
        int buf = it & 1;
        if (it == NIT - 1) CP_WAIT0(); else CP_WAIT1();
        __syncthreads();
        const __half* At = Ab + (size_t)buf * 256 * VKP;
        const __half* Bt = Bb + (size_t)buf * 64 * VKP;
        F16_STEP_MKNK(At, Bt, wm, wn, j, r);
        __syncthreads();
        if (it + 2 < NIT) prefetch(buf, (it + 2) * 64);
    }

    // ---- slab store (smem) ----
    const int g = lane >> 2;
#pragma unroll
    for (int mi = 0; mi < 4; mi++)
#pragma unroll
        for (int r2 = 0; r2 < 2; r2++) {
            int c = wm + mi * 16 + g + r2 * 8;
#pragma unroll
            for (int ni = 0; ni < 4; ni++) {
                int nl = wn + ni * 8 + t * 2;
                *(__half2*)(Sl + (size_t)c * VKP + nl) = __floats2half2_rn(
                    acc[mi][ni][r2 * 2 + 0], acc[mi][ni][r2 * 2 + 1]);
            }
        }
    __syncthreads();

    // ---- phase 2: gate conv (single-buffered Wg tiles) ----
    REINIT_ACC;
    for (int kt = 0; kt < 4; kt++) {
#pragma unroll
        for (int p = 0; p < 8; p++) {
            int row = lrow + 32 * p;
            const __half* gp = WgH + (size_t)row * Cdim + kt * 64 + lcc * 8;
            __half* sp = Wa + (size_t)row * VKP + lcc * 8;
            CP_ASYNC16(smem_cast(sp), gp);
        }
        CP_COMMIT();
        CP_WAIT0();
        __syncthreads();
        const __half* Bt = Sl + (size_t)(kt * 64) * VKP;   // B = slab [k=c][n]
        F16_STEP_MKKN(Wa, Bt, VKP, wm, wn, j, r);
        __syncthreads();
    }

    // ---- gate epilogue ----
#pragma unroll
    for (int mi = 0; mi < 4; mi++)
#pragma unroll
        for (int r2 = 0; r2 < 2; r2++) {
            int o = wm + mi * 16 + g + r2 * 8;
            float bi = bg[o];
#pragma unroll
            for (int ni = 0; ni < 4; ni++) {
                int nl = wn + ni * 8 + t * 2;
                __half2 xh = *(const __half2*)(Sl + (size_t)o * VKP + nl);
                float x0 = __low2float(xh), x1 = __high2float(xh);
                float g0 = acc[mi][ni][r2 * 2 + 0] + bi;
                float g1 = acc[mi][ni][r2 * 2 + 1] + bi;
                *(__half2*)(F + (size_t)o * Ndim + n0 + nl) = __floats2half2_rn(
                    x0 / (1.f + __expf(-g0)),
                    x1 / (1.f + __expf(-g1)));
            }
        }
}

// =====================================================================
// final fp16 (R12 form): out = WoH @ (F0+F1+F2) + bo. grid (18, 2, 4)
// =====================================================================
__global__ void __launch_bounds__(256, 2) final_h(
    const __half* __restrict__ WoH, const float* __restrict__ bo,
    float* __restrict__ out)
{
    extern __shared__ __half hsm[];
    __half* Ab = hsm;                     // [2][128][VKP]
    __half* Bb = hsm + 2 * 128 * VKP;     // [2][64][SKP]

    const int b  = blockIdx.z;
    const int o0 = blockIdx.y * BM;
    const int n0 = blockIdx.x * BN;
    const int tid = threadIdx.x;
    const int warp = tid >> 5, lane = tid & 31;
    const int g = lane >> 2, t = lane & 3;
    const int jj = lane >> 3, rr = lane & 7;
    const int wm = (warp & 1) * 64, wn = (warp >> 1) * 32;
    const __half* F0 = g_F3h[0] + (size_t)b * CN;
    const __half* F1 = g_F3h[1] + (size_t)b * CN;
    const __half* F2 = g_F3h[2] + (size_t)b * CN;
    float* dst = out + (size_t)b * CN;

    const int u = tid & 127;
    const bool isB = (tid >= 128);
    const int r0a = u >> 3, cca = u & 7;
    const int r0b = u >> 4, ccb = u & 15;

    auto prefetchA = [&](int bufp, int k0) {
        if (!isB) {
#pragma unroll
            for (int p = 0; p < 8; p++) {
                int row = r0a + 16 * p;
                const __half* gp = WoH + (size_t)(o0 + row) * Cdim + k0 + cca * 8;
                __half* sp = Ab + ((size_t)bufp * 128 + row) * VKP + cca * 8;
                CP_ASYNC16(smem_cast(sp), gp);
            }
        }
        CP_COMMIT();
    };

    __half2 breg[8][4];
    auto loadB = [&](int k0) {
        if (isB) {
#pragma unroll
            for (int p = 0; p < 8; p++) {
                int row = r0b + 8 * p;
                size_t off = (size_t)(k0 + row) * Ndim + n0 + ccb * 8;
#pragma unroll
                for (int c = 0; c < 4; c++) {
                    float2 a0 = __half22float2(*(const __half2*)(F0 + off + c * 2));
                    float2 a1 = __half22float2(*(const __half2*)(F1 + off + c * 2));
                    float2 a2 = __half22float2(*(const __half2*)(F2 + off + c * 2));
                    breg[p][c] = __floats2half2_rn(a0.x + a1.x + a2.x,
                                                   a0.y + a1.y + a2.y);
                }
            }
        }
    };
    auto storeB = [&](int bufp) {
        if (isB) {
#pragma unroll
            for (int p = 0; p < 8; p++) {
                int row = r0b + 8 * p;
                __half2* sp = (__half2*)(Bb + ((size_t)bufp * 64 + row) * SKP + ccb * 8);
#pragma unroll
                for (int c = 0; c < 4; c++) sp[c] = breg[p][c];
            }
        }
    };

    DECL_ACC;

    prefetchA(0, 0);
    prefetchA(1, 64);
    loadB(0); storeB(0);
    loadB(64);
    const int NIT = Cdim / 64;   // 4
    for (int it = 0; it < NIT; it++) {
        int buf = it & 1;
        if (it == NIT - 1) CP_WAIT0(); else CP_WAIT1();
        __syncthreads();
        const __half* At = Ab + (size_t)buf * 128 * VKP;
        const __half* Bt = Bb + (size_t)buf * 64 * SKP;
        F16_STEP_MKKN(At, Bt, SKP, wm, wn, jj, rr);
        __syncthreads();
        if (it + 2 < NIT) prefetchA(buf, (it + 2) * 64);
        if (it + 1 < NIT) storeB(buf ^ 1);
        if (it + 2 < NIT) loadB((it + 2) * 64);
    }

#pragma unroll
    for (int mi = 0; mi < 4; mi++)
#pragma unroll
        for (int r2 = 0; r2 < 2; r2++) {
            int o = o0 + wm + mi * 16 + g + r2 * 8;
            float bi = bo[o];
#pragma unroll
            for (int ni = 0; ni < 4; ni++) {
                int n = n0 + wn + ni * 8 + t * 2;
                size_t idx = (size_t)o * Ndim + n;
                float2 v = { acc[mi][ni][r2 * 2 + 0] + bi,
                             acc[mi][ni][r2 * 2 + 1] + bi };
                *(float2*)(dst + idx) = v;
            }
        }
}

// =====================================================================
// launch
// =====================================================================
extern "C" void kernel_launch(void* const* d_in, const int* in_sizes, int n_in,
                              void* d_out, int out_size)
{
    const float* x[3] = { (const float*)d_in[0], (const float*)d_in[1], (const float*)d_in[2] };
    const float* s = (const float*)d_in[3];
    const float *wq[3], *bq[3], *wk[3], *bk[3], *wv[3], *bv[3];
    for (int m = 0; m < 3; m++) {
        wq[m] = (const float*)d_in[4 + 6 * m];
        bq[m] = (const float*)d_in[5 + 6 * m];
        wk[m] = (const float*)d_in[6 + 6 * m];
        bk[m] = (const float*)d_in[7 + 6 * m];
        wv[m] = (const float*)d_in[8 + 6 * m];
        bv[m] = (const float*)d_in[9 + 6 * m];
    }
    const float* wg = (const float*)d_in[22];
    const float* bg = (const float*)d_in[23];
    const float* wo = (const float*)d_in[24];
    const float* bo = (const float*)d_in[25];
    float* out = (float*)d_out;

    __half *gH, *gXh, *gWT, *gKh;
    cudaGetSymbolAddress((void**)&gH,  g_H);
    cudaGetSymbolAddress((void**)&gXh, g_Xh);
    cudaGetSymbolAddress((void**)&gWT, g_WT);
    cudaGetSymbolAddress((void**)&gKh, g_Kh);

    __half *Kh[3], *Qh[3], *KSh[3], *Vh[3], *Xh[3];
    for (int m = 0; m < 3; m++) {
        Kh[m]  = gKh + (size_t)m * PLANE;
        Qh[m]  = gH + (size_t)(0 + m) * PLANE;
        KSh[m] = gH + (size_t)(3 + m) * PLANE;
        Vh[m]  = gH + (size_t)(6 + m) * PLANE;
        Xh[m]  = gXh + (size_t)m * PLANE;
    }
    __half* WqH[3]; __half* WkH[3]; __half* WvH[3];
    for (int m = 0; m < 3; m++) {
        WqH[m] = gWT + (size_t)(3 * m + 0) * Cdim * Cdim;
        WkH[m] = gWT + (size_t)(3 * m + 1) * Cdim * Cdim;
        WvH[m] = gWT + (size_t)(3 * m + 2) * Cdim * Cdim;
    }
    __half* WgH = gWT + (size_t)9 * Cdim * Cdim;
    __half* WoH = gWT + (size_t)10 * Cdim * Cdim;

    W11 WC;
    for (int m = 0; m < 3; m++) {
        WC.src[3 * m + 0] = wq[m];
        WC.src[3 * m + 1] = wk[m];
        WC.src[3 * m + 2] = wv[m];
    }
    WC.src[9]  = wg;
    WC.src[10] = wo;

    Proj9 P;
    for (int m = 0; m < 3; m++) {
        P.X[3 * m + 0] = Xh[m]; P.W[3 * m + 0] = WqH[m]; P.B[3 * m + 0] = bq[m];
        P.DH[3 * m + 0] = Qh[m]; P.sidx[3 * m + 0] = m;
        P.X[3 * m + 1] = Xh[m]; P.W[3 * m + 1] = WkH[m]; P.B[3 * m + 1] = bk[m];
        P.DH[3 * m + 1] = Kh[m]; P.sidx[3 * m + 1] = m;
        P.X[3 * m + 2] = Xh[m]; P.W[3 * m + 2] = WvH[m]; P.B[3 * m + 2] = bv[m];
        P.DH[3 * m + 2] = Vh[m]; P.sidx[3 * m + 2] = -1;
    }

    // attends: w_rgb(Q0; K2+K1; V0), w_depth(Q2; K0+K1; V2), w_thermal(Q1; K0+K2; V1)
    Att3h A;
    const int qi[3] = { 0, 2, 1 };
    for (int a = 0; a < 3; a++) {
        A.Q[a]  = Qh[qi[a]];
        A.KS[a] = KSh[a];
        A.V[a]  = Vh[qi[a]];
    }

    cudaFuncSetAttribute(proj_h9,  cudaFuncAttributeMaxDynamicSharedMemorySize, PJ_SMEM);
    cudaFuncSetAttribute(scores_h, cudaFuncAttributeMaxDynamicSharedMemorySize, SC_SMEM);
    cudaFuncSetAttribute(avgate_h, cudaFuncAttributeMaxDynamicSharedMemorySize, AV_SMEM);
    cudaFuncSetAttribute(final_h,  cudaFuncAttributeMaxDynamicSharedMemorySize, PJ_SMEM);

    dim3 blk(256);
    cvt_x3 <<<dim3(PLANE / 1024, 3), blk>>>(x[0], x[1], x[2], Xh[0], Xh[1], Xh[2]);
    cvt_w11<<<dim3(Cdim * Cdim / 1024, 11), blk>>>(WC, gWT);
    proj_h9<<<dim3(Ndim / BN, Cdim / BM, 36), blk, PJ_SMEM>>>(P, s);
    ksum3_kernel<<<dim3(PLANE / 1024), blk>>>(Kh[0], Kh[1], Kh[2], KSh[0], KSh[1], KSh[2]);
    scores_h<<<dim3(Ndim / BN, Ndim / BM, 12), blk, SC_SMEM>>>(A);
    softmax_kernel<<<dim3(3 * Bdim * Ndim / 2), blk>>>();
    avgate_h<<<dim3(Ndim / 64, 1, 12), blk, AV_SMEM>>>(A, WgH, bg);
    final_h<<<dim3(Ndim / BN, Cdim / BM, 4), blk, PJ_SMEM>>>(WoH, bo, out);
}